// round 10
// baseline (speedup 1.0000x reference)
#include <cuda_runtime.h>
#include <cuda_bf16.h>
#include <math.h>
#include <stdint.h>

// ---------------- problem constants ----------------
#define Bsz 8192
#define Dd  1024
#define Uu  512
#define Ff  4
#define Ee  4
#define Tt  2
#define Gg  5
#define NEXP 17

// ---------------- scratch ----------------
__device__ float g_common[Bsz * Uu];
__device__ float g_field [Bsz * Ff * Uu];
__device__ float g_logits[Bsz * Tt * Gg];
__device__ int   g_idx[Ff * Ee][Bsz];
__device__ int   g_cnt[Ff * Ee];
__device__ __nv_bfloat16 g_xhi[Bsz * Dd];
__device__ __nv_bfloat16 g_xlo[Bsz * Dd];
__device__ __nv_bfloat16 g_whi[(size_t)NEXP * Uu * Dd];   // [ez][u][d]
__device__ __nv_bfloat16 g_wlo[(size_t)NEXP * Uu * Dd];

// ---------------- GEMM config ----------------
// CTA tile 128(m) x 256(n), 512 threads (16 warps), warp tile 64x32.
// BK=32 bf16 (64B rows, SW64), 2 stages x 48KB.
#define BM 128
#define BN 256
#define NCH 32
#define NTH 512
#define AHI 0
#define ALO 8192
#define BHI 16384
#define BLO 32768
#define STAGE 49152
#define NSTG 2
#define IDX_OFF (NSTG * STAGE)
#define DSM_TOTAL (NSTG * STAGE + 1024)

#define SWZ64(o) ((o) ^ (((o) >> 3) & 0x30))

__device__ __forceinline__ uint32_t s2u(const void* p) {
    return (uint32_t)__cvta_generic_to_shared(p);
}

__device__ __forceinline__ void cpa16(uint32_t dst, const void* src) {
    asm volatile("cp.async.cg.shared.global [%0], [%1], 16;"
                 :: "r"(dst), "l"(__cvta_generic_to_global(src)));
}
#define CP_COMMIT() asm volatile("cp.async.commit_group;" ::: "memory")
#define CP_WAIT(n)  asm volatile("cp.async.wait_group %0;" :: "n"(n) : "memory")

__device__ __forceinline__ void ldsm4(uint32_t* r, uint32_t addr) {
    asm volatile("ldmatrix.sync.aligned.m8n8.x4.shared.b16 {%0,%1,%2,%3}, [%4];"
                 : "=r"(r[0]), "=r"(r[1]), "=r"(r[2]), "=r"(r[3]) : "r"(addr));
}

__device__ __forceinline__ void mma16816(float* c, const uint32_t* a, uint32_t b0, uint32_t b1) {
    asm volatile(
        "mma.sync.aligned.m16n8k16.row.col.f32.bf16.bf16.f32 "
        "{%0,%1,%2,%3}, {%4,%5,%6,%7}, {%8,%9}, {%0,%1,%2,%3};"
        : "+f"(c[0]), "+f"(c[1]), "+f"(c[2]), "+f"(c[3])
        : "r"(a[0]), "r"(a[1]), "r"(a[2]), "r"(a[3]), "r"(b0), "r"(b1));
}

// issue one k-chunk (32 k-elems) of cp.async loads into stage ch&1
__device__ __forceinline__ void issue_chunk(uint32_t sb, int ch,
                                            const __nv_bfloat16* __restrict__ wbh,
                                            const __nv_bfloat16* __restrict__ wbl,
                                            const int* __restrict__ sidx,
                                            int m0, int n0, int tid)
{
    uint32_t st = sb + (uint32_t)(ch & (NSTG - 1)) * STAGE;
    const int kbase = ch * 32;
    // A: 128 rows x 64B (hi & lo) = 512 16B units each; 1 per thread
    {
        int r = tid >> 2, c = tid & 3;
        int grow = sidx ? sidx[r] : (m0 + r);
        size_t go = (size_t)grow * Dd + kbase + c * 8;
        uint32_t so = SWZ64(r * 64 + c * 16);
        cpa16(st + AHI + so, g_xhi + go);
        cpa16(st + ALO + so, g_xlo + go);
    }
    // B: 256 rows x 64B (hi & lo) = 1024 units each; 2 per thread
#pragma unroll
    for (int i = 0; i < 2; i++) {
        int u = tid + i * NTH, r = u >> 2, c = u & 3;
        size_t go = (size_t)(n0 + r) * Dd + kbase + c * 8;
        uint32_t so = SWZ64(r * 64 + c * 16);
        cpa16(st + BHI + so, wbh + go);
        cpa16(st + BLO + so, wbl + go);
    }
    CP_COMMIT();
}

// ============================================================
// prep kernels
// ============================================================
__global__ void zero_kernel()
{
    int i = blockIdx.x * blockDim.x + threadIdx.x;     // float4 idx over discrete half
    int b = i >> 8, r = i & 255;
    ((float4*)g_field)[(size_t)b * (Ff * Uu / 4) + r] = make_float4(0.f, 0.f, 0.f, 0.f);
    if (i < Ff * Ee) g_cnt[i] = 0;
}

__global__ void build_idx(const float* __restrict__ x)
{
    int b = blockIdx.x * blockDim.x + threadIdx.x;
    if (b >= Bsz) return;
    const float* xr = x + (size_t)b * Dd;
#pragma unroll
    for (int f = 0; f < 2; f++)
#pragma unroll
        for (int e = 0; e < 4; e++)
            if (xr[f * 4 + e] > 0.f) {
                int p = atomicAdd(&g_cnt[f * 4 + e], 1);
                g_idx[f * 4 + e][p] = b;
            }
#pragma unroll
    for (int f = 2; f < 4; f++) {
        float v = xr[8 + (f - 2)];
        int e = (v <= -0.5f) ? 0 : (v <= 0.f) ? 1 : (v <= 0.5f) ? 2 : 3;
        int p = atomicAdd(&g_cnt[f * 4 + e], 1);
        g_idx[f * 4 + e][p] = b;
    }
}

__global__ void splitx_kernel(const float* __restrict__ x)
{
    int i = blockIdx.x * blockDim.x + threadIdx.x;
    float4 v = ((const float4*)x)[i];
    int o = i * 4;
    float vv[4] = {v.x, v.y, v.z, v.w};
#pragma unroll
    for (int k = 0; k < 4; k++) {
        __nv_bfloat16 hi = __float2bfloat16_rn(vv[k]);
        float lo = vv[k] - __bfloat162float(hi);
        g_xhi[o + k] = hi;
        g_xlo[o + k] = __float2bfloat16_rn(lo);
    }
}

__global__ void splitw_kernel(const float* __restrict__ Wc, const float* __restrict__ We)
{
    __shared__ float t[32][33];
    int ez = blockIdx.z;
    const float* src = (ez == 0) ? Wc : (We + (size_t)(ez - 1) * Dd * Uu);
    int u0 = blockIdx.x * 32, d0 = blockIdx.y * 32;
    int tx = threadIdx.x, ty = threadIdx.y;
#pragma unroll
    for (int k = 0; k < 32; k += 8)
        t[ty + k][tx] = src[(size_t)(d0 + ty + k) * Uu + u0 + tx];
    __syncthreads();
#pragma unroll
    for (int k = 0; k < 32; k += 8) {
        int u = u0 + ty + k, d = d0 + tx;
        float v = t[tx][ty + k];
        __nv_bfloat16 hi = __float2bfloat16_rn(v);
        float lo = v - __bfloat162float(hi);
        size_t o = (size_t)ez * Uu * Dd + (size_t)u * Dd + d;
        g_whi[o] = hi;
        g_wlo[o] = __float2bfloat16_rn(lo);
    }
}

// gate logits: g_logits[b][t][g] = x[b,:] . Wg[t,:,g] + bg[t,g]
__global__ __launch_bounds__(256) void glogits_kernel(
    const float* __restrict__ x, const float* __restrict__ Wg,
    const float* __restrict__ bg)
{
    __shared__ float wgs[Dd * Tt * Gg];   // 40KB
    const int tid = threadIdx.x;
    for (int i = tid; i < Dd * Tt * Gg; i += 256) {
        int d = i / (Tt * Gg), tg = i - d * (Tt * Gg);
        int t = tg / Gg, g = tg - t * Gg;
        wgs[i] = Wg[((size_t)t * Dd + d) * Gg + g];
    }
    __syncthreads();

    const int w = tid >> 5, lane = tid & 31;
    int b = blockIdx.x * 8 + w;
    const float* xr = x + (size_t)b * Dd;
    float acc[Tt * Gg];
#pragma unroll
    for (int j = 0; j < Tt * Gg; j++) acc[j] = 0.f;
    for (int k = lane; k < Dd; k += 32) {
        float xv = xr[k];
        const float* wr = wgs + k * (Tt * Gg);
#pragma unroll
        for (int j = 0; j < Tt * Gg; j++) acc[j] = fmaf(xv, wr[j], acc[j]);
    }
#pragma unroll
    for (int j = 0; j < Tt * Gg; j++) {
#pragma unroll
        for (int o = 16; o; o >>= 1) acc[j] += __shfl_xor_sync(0xffffffffu, acc[j], o);
    }
    if (lane < Tt * Gg) {
        int t = lane / Gg, g = lane - t * Gg;
        g_logits[(size_t)b * (Tt * Gg) + lane] = acc[lane] + bg[t * Gg + g];
    }
}

// ============================================================
// GEMM mainloop: 2-stage, BK=32, 16 warps, warp tile 64x32.
// Fragment sequencing keeps <=40 frag regs live (fits 128-reg cap).
// ============================================================
__device__ __forceinline__ void gemm_mainloop(
    uint32_t sb, const __nv_bfloat16* wbh, const __nv_bfloat16* wbl,
    const int* sidx, int m0, int n0, int tid, int lane, int wm, int wn,
    float acc[4][4][4])
{
    const int lrow = (lane & 7) + ((lane >> 3) & 1) * 8;
    const int kb   = lane >> 4;

    issue_chunk(sb, 0, wbh, wbl, sidx, m0, n0, tid);

    for (int ch = 0; ch < NCH; ch++) {
        if (ch + 1 < NCH) {
            issue_chunk(sb, ch + 1, wbh, wbl, sidx, m0, n0, tid);
            CP_WAIT(1);
        } else {
            CP_WAIT(0);
        }
        __syncthreads();

        uint32_t s0 = sb + (uint32_t)(ch & (NSTG - 1)) * STAGE;
#pragma unroll
        for (int ks = 0; ks < 2; ks++) {
            uint32_t koff = (uint32_t)(ks * 2 + kb) * 16;
            uint32_t ahi[4][4], bhi[2][4];
#pragma unroll
            for (int mi = 0; mi < 4; mi++)
                ldsm4(ahi[mi], s0 + AHI + SWZ64((uint32_t)(wm + mi * 16 + lrow) * 64 + koff));
#pragma unroll
            for (int nj = 0; nj < 2; nj++)
                ldsm4(bhi[nj], s0 + BHI + SWZ64((uint32_t)(wn + nj * 16 + lrow) * 64 + koff));
            // hi * hi
#pragma unroll
            for (int mi = 0; mi < 4; mi++)
#pragma unroll
                for (int nj = 0; nj < 2; nj++) {
                    mma16816(acc[mi][2*nj],   ahi[mi], bhi[nj][0], bhi[nj][2]);
                    mma16816(acc[mi][2*nj+1], ahi[mi], bhi[nj][1], bhi[nj][3]);
                }
            // hi * lo
            {
                uint32_t blo[2][4];
#pragma unroll
                for (int nj = 0; nj < 2; nj++)
                    ldsm4(blo[nj], s0 + BLO + SWZ64((uint32_t)(wn + nj * 16 + lrow) * 64 + koff));
#pragma unroll
                for (int mi = 0; mi < 4; mi++)
#pragma unroll
                    for (int nj = 0; nj < 2; nj++) {
                        mma16816(acc[mi][2*nj],   ahi[mi], blo[nj][0], blo[nj][2]);
                        mma16816(acc[mi][2*nj+1], ahi[mi], blo[nj][1], blo[nj][3]);
                    }
            }
            // lo * hi (bhi still live; ahi regs reused for alo)
            {
                uint32_t alo[4][4];
#pragma unroll
                for (int mi = 0; mi < 4; mi++)
                    ldsm4(alo[mi], s0 + ALO + SWZ64((uint32_t)(wm + mi * 16 + lrow) * 64 + koff));
#pragma unroll
                for (int mi = 0; mi < 4; mi++)
#pragma unroll
                    for (int nj = 0; nj < 2; nj++) {
                        mma16816(acc[mi][2*nj],   alo[mi], bhi[nj][0], bhi[nj][2]);
                        mma16816(acc[mi][2*nj+1], alo[mi], bhi[nj][1], bhi[nj][3]);
                    }
            }
        }
        __syncthreads();
    }
}

// ---------------- merged GEMM: z=0 common (dense), z>=1 expert (gathered) ----
__global__ __launch_bounds__(NTH, 1) void gemm_all(
    const float* __restrict__ bc, const float* __restrict__ be)
{
    extern __shared__ __align__(1024) char dsm[];
    const int z = blockIdx.z;
    const bool dense = (z == 0);
    const int fe = z - 1;
    const int t0 = blockIdx.x * BM;
    int cnt = 0;
    if (!dense) {
        cnt = g_cnt[fe];
        if (t0 >= cnt) return;
    }

    const int tid = threadIdx.x;
    const int w = tid >> 5, lane = tid & 31;
    const int n0 = blockIdx.y * BN;
    const int wm = (w & 1) * 64;          // 2 m-slots
    const int wn = (w >> 1) * 32;         // 8 n-slots
    uint32_t sb = s2u(dsm);
    int* sidx = (int*)(dsm + IDX_OFF);

    if (!dense) {
        if (tid < BM) {
            int s = t0 + tid;
            sidx[tid] = g_idx[fe][(s < cnt) ? s : (cnt - 1)];
        }
        __syncthreads();
    }

    const int ez = dense ? 0 : (1 + fe);
    const __nv_bfloat16* wbh = g_whi + (size_t)ez * Uu * Dd;
    const __nv_bfloat16* wbl = g_wlo + (size_t)ez * Uu * Dd;

    float acc[4][4][4];
#pragma unroll
    for (int mi = 0; mi < 4; mi++)
#pragma unroll
        for (int ni = 0; ni < 4; ni++)
#pragma unroll
            for (int j = 0; j < 4; j++) acc[mi][ni][j] = 0.f;

    gemm_mainloop(sb, wbh, wbl, dense ? nullptr : sidx, t0, n0, tid, lane, wm, wn, acc);

    if (dense) {
        const float* bep = bc + n0;
#pragma unroll
        for (int mi = 0; mi < 4; mi++) {
#pragma unroll
            for (int h = 0; h < 2; h++) {
                int rl = wm + mi * 16 + (lane >> 2) + h * 8;
                float* gp = g_common + (size_t)(t0 + rl) * Uu + n0;
#pragma unroll
                for (int ni = 0; ni < 4; ni++) {
                    int cl = wn + ni * 8 + (lane & 3) * 2;
                    float v0 = fmaxf(acc[mi][ni][h * 2 + 0] + bep[cl],     0.f);
                    float v1 = fmaxf(acc[mi][ni][h * 2 + 1] + bep[cl + 1], 0.f);
                    *(float2*)(gp + cl) = make_float2(v0, v1);
                }
            }
        }
    } else {
        const int f = fe >> 2;
        const float* bep = be + (size_t)fe * Uu + n0;
        const bool atom = (f < 2);
#pragma unroll
        for (int mi = 0; mi < 4; mi++) {
#pragma unroll
            for (int h = 0; h < 2; h++) {
                int rl = wm + mi * 16 + (lane >> 2) + h * 8;
                if (t0 + rl >= cnt) continue;
                int grow = sidx[rl];
                float* gp = g_field + (size_t)grow * (Ff * Uu) + (size_t)f * Uu + n0;
#pragma unroll
                for (int ni = 0; ni < 4; ni++) {
                    int cl = wn + ni * 8 + (lane & 3) * 2;
                    float v0 = fmaxf(acc[mi][ni][h * 2 + 0] + bep[cl],     0.f);
                    float v1 = fmaxf(acc[mi][ni][h * 2 + 1] + bep[cl + 1], 0.f);
                    if (atom) {
                        atomicAdd(gp + cl,     v0);
                        atomicAdd(gp + cl + 1, v1);
                    } else {
                        *(float2*)(gp + cl) = make_float2(v0, v1);
                    }
                }
            }
        }
    }
}

// ============================================================
// fused per-row epilogue: att/upd dots + softmax + mix
// ============================================================
__global__ __launch_bounds__(256) void epilogue_kernel(
    const float* __restrict__ Wa, const float* __restrict__ ba,
    const float* __restrict__ Wu, const float* __restrict__ bu,
    float* __restrict__ out)
{
    const int b = blockIdx.x;
    __shared__ float cs[Uu];
    __shared__ float fs[Ff][Uu];
    __shared__ float s_att[Ff], s_upd[Ff];
    __shared__ float s_gates[Tt][Gg];

    const int tid = threadIdx.x;
    for (int i = tid; i < Uu; i += 256)
        cs[i] = g_common[(size_t)b * Uu + i];
    for (int i = tid; i < Ff * Uu; i += 256)
        fs[0][i] = g_field[(size_t)b * Ff * Uu + i];
    __syncthreads();

    const int w = tid >> 5, lane = tid & 31;

    {
        int f = w >> 1;
        const float* Wv = (w & 1) ? (Wu + (size_t)f * 2 * Uu) : (Wa + (size_t)f * 2 * Uu);
        float s = 0.f;
        for (int k = lane; k < Uu; k += 32) s = fmaf(cs[k],    Wv[k],      s);
        for (int k = lane; k < Uu; k += 32) s = fmaf(fs[f][k], Wv[Uu + k], s);
#pragma unroll
        for (int o = 16; o; o >>= 1) s += __shfl_xor_sync(0xffffffffu, s, o);
        if (lane == 0) {
            float bv = (w & 1) ? bu[f] : ba[f];
            float v = 1.f / (1.f + expf(-(s + bv)));
            if (w & 1) s_upd[f] = v; else s_att[f] = v;
        }
    }
    __syncthreads();

    if (tid < Tt) {
        const float* lg = g_logits + (size_t)b * (Tt * Gg) + tid * Gg;
        float mx = lg[0];
#pragma unroll
        for (int g = 1; g < Gg; g++) mx = fmaxf(mx, lg[g]);
        float ex[Gg], sum = 0.f;
#pragma unroll
        for (int g = 0; g < Gg; g++) { ex[g] = expf(lg[g] - mx); sum += ex[g]; }
        float inv = 1.f / sum;
#pragma unroll
        for (int g = 0; g < Gg; g++) s_gates[tid][g] = ex[g] * inv;
    }
    __syncthreads();

    for (int u = tid; u < Uu; u += 256) {
        float c = cs[u];
        float ffv[Ff];
#pragma unroll
        for (int f = 0; f < Ff; f++) {
            float fo = fs[f][u];
            float fa = s_att[f] * fo;
            ffv[f] = s_upd[f] * fa + (1.f - s_upd[f]) * c;
        }
#pragma unroll
        for (int t = 0; t < Tt; t++) {
            float o = s_gates[t][0] * c;
#pragma unroll
            for (int fq = 0; fq < Ff; fq++) o = fmaf(s_gates[t][1 + fq], ffv[fq], o);
            out[((size_t)b * Tt + t) * Uu + u] = o;
        }
    }
}

// ============================================================
// launch
// ============================================================
extern "C" void kernel_launch(void* const* d_in, const int* in_sizes, int n_in,
                              void* d_out, int out_size)
{
    const float* x  = (const float*)d_in[0];
    const float* Wc = (const float*)d_in[1];
    const float* bc = (const float*)d_in[2];
    const float* We = (const float*)d_in[3];
    const float* be = (const float*)d_in[4];
    const float* Wg = (const float*)d_in[5];
    const float* bg = (const float*)d_in[6];
    const float* Wa = (const float*)d_in[7];
    const float* ba = (const float*)d_in[8];
    const float* Wu = (const float*)d_in[9];
    const float* bu = (const float*)d_in[10];
    float* out = (float*)d_out;

    cudaFuncSetAttribute(gemm_all, cudaFuncAttributeMaxDynamicSharedMemorySize, DSM_TOTAL);

    zero_kernel<<<(Bsz * 2 * Uu / 4) / 256, 256>>>();
    build_idx<<<Bsz / 256, 256>>>(x);
    splitx_kernel<<<(Bsz * Dd / 4) / 256, 256>>>(x);
    splitw_kernel<<<dim3(Uu / 32, Dd / 32, NEXP), dim3(32, 8)>>>(Wc, We);
    glogits_kernel<<<Bsz / 8, 256>>>(x, Wg, bg);
    gemm_all<<<dim3(Bsz / BM, Uu / BN, 1 + Ff * Ee), NTH, DSM_TOTAL>>>(bc, be);
    epilogue_kernel<<<Bsz, 256>>>(Wa, ba, Wu, bu, out);
}

// round 11
// speedup vs baseline: 1.9694x; 1.9694x over previous
#include <cuda_runtime.h>
#include <cuda_fp16.h>
#include <math.h>
#include <stdint.h>

// ---------------- problem constants ----------------
#define Bsz 8192
#define Dd  1024
#define Uu  512
#define Ff  4
#define Ee  4
#define Tt  2
#define Gg  5
#define NEXP 17

// ---------------- scratch ----------------
__device__ float g_common[Bsz * Uu];
__device__ float g_field [Bsz * Ff * Uu];
__device__ float g_logits[Bsz * Tt * Gg];
__device__ int   g_idx[Ff * Ee][Bsz];
__device__ int   g_cnt[Ff * Ee];
__device__ __half g_xh[Bsz * Dd];                     // fp16 x
__device__ __half g_wh[(size_t)NEXP * Uu * Dd];       // fp16 W, transposed [ez][u][d]

// ---------------- GEMM config (R7-proven structure, single fp16 term) ----
#define BM 128
#define BN 256
#define NCH 16
#define AOF 0
#define BOF 16384
#define STAGE 49152
#define NSTG 2
#define IDX_OFF (NSTG * STAGE)
#define DSM_TOTAL (NSTG * STAGE + 1024)

#define SWZ(o) ((o) ^ (((o) >> 3) & 0x70))

__device__ __forceinline__ uint32_t s2u(const void* p) {
    return (uint32_t)__cvta_generic_to_shared(p);
}

__device__ __forceinline__ void cpa16(uint32_t dst, const void* src) {
    asm volatile("cp.async.cg.shared.global [%0], [%1], 16;"
                 :: "r"(dst), "l"(__cvta_generic_to_global(src)));
}
#define CP_COMMIT() asm volatile("cp.async.commit_group;" ::: "memory")
#define CP_WAIT(n)  asm volatile("cp.async.wait_group %0;" :: "n"(n) : "memory")

__device__ __forceinline__ void ldsm4(uint32_t* r, uint32_t addr) {
    asm volatile("ldmatrix.sync.aligned.m8n8.x4.shared.b16 {%0,%1,%2,%3}, [%4];"
                 : "=r"(r[0]), "=r"(r[1]), "=r"(r[2]), "=r"(r[3]) : "r"(addr));
}

__device__ __forceinline__ void mma16816(float* c, const uint32_t* a, uint32_t b0, uint32_t b1) {
    asm volatile(
        "mma.sync.aligned.m16n8k16.row.col.f32.f16.f16.f32 "
        "{%0,%1,%2,%3}, {%4,%5,%6,%7}, {%8,%9}, {%0,%1,%2,%3};"
        : "+f"(c[0]), "+f"(c[1]), "+f"(c[2]), "+f"(c[3])
        : "r"(a[0]), "r"(a[1]), "r"(a[2]), "r"(a[3]), "r"(b0), "r"(b1));
}

// issue one k-chunk (64 k-elems) of cp.async loads into stage ch&1
__device__ __forceinline__ void issue_chunk(uint32_t sb, int ch,
                                            const __half* __restrict__ wb,
                                            const int* __restrict__ sidx,
                                            int m0, int n0, int tid)
{
    uint32_t st = sb + (uint32_t)(ch & (NSTG - 1)) * STAGE;
    const int kbase = ch * 64;
    // A: 128 rows x 128B = 1024 16B-units
#pragma unroll
    for (int i = 0; i < 4; i++) {
        int u = tid + i * 256, r = u >> 3, cc = u & 7;
        int grow = sidx ? sidx[r] : (m0 + r);
        size_t go = (size_t)grow * Dd + kbase + cc * 8;
        cpa16(st + AOF + SWZ(r * 128 + cc * 16), g_xh + go);
    }
    // B: 256 rows x 128B = 2048 16B-units
#pragma unroll
    for (int i = 0; i < 8; i++) {
        int u = tid + i * 256, r = u >> 3, cc = u & 7;
        size_t go = (size_t)(n0 + r) * Dd + kbase + cc * 8;
        cpa16(st + BOF + SWZ(r * 128 + cc * 16), wb + go);
    }
    CP_COMMIT();
}

// ============================================================
// prep kernels
// ============================================================
__global__ void zero_kernel()
{
    int i = blockIdx.x * blockDim.x + threadIdx.x;     // float4 idx over discrete half
    int b = i >> 8, r = i & 255;
    ((float4*)g_field)[(size_t)b * (Ff * Uu / 4) + r] = make_float4(0.f, 0.f, 0.f, 0.f);
    if (i < Ff * Ee) g_cnt[i] = 0;
}

__global__ void build_idx(const float* __restrict__ x)
{
    int b = blockIdx.x * blockDim.x + threadIdx.x;
    if (b >= Bsz) return;
    const float* xr = x + (size_t)b * Dd;
#pragma unroll
    for (int f = 0; f < 2; f++)
#pragma unroll
        for (int e = 0; e < 4; e++)
            if (xr[f * 4 + e] > 0.f) {
                int p = atomicAdd(&g_cnt[f * 4 + e], 1);
                g_idx[f * 4 + e][p] = b;
            }
#pragma unroll
    for (int f = 2; f < 4; f++) {
        float v = xr[8 + (f - 2)];
        int e = (v <= -0.5f) ? 0 : (v <= 0.f) ? 1 : (v <= 0.5f) ? 2 : 3;
        int p = atomicAdd(&g_cnt[f * 4 + e], 1);
        g_idx[f * 4 + e][p] = b;
    }
}

__global__ void splitx_kernel(const float* __restrict__ x)
{
    int i = blockIdx.x * blockDim.x + threadIdx.x;
    float4 v = ((const float4*)x)[i];
    int o = i * 4;
    g_xh[o + 0] = __float2half_rn(v.x);
    g_xh[o + 1] = __float2half_rn(v.y);
    g_xh[o + 2] = __float2half_rn(v.z);
    g_xh[o + 3] = __float2half_rn(v.w);
}

__global__ void splitw_kernel(const float* __restrict__ Wc, const float* __restrict__ We)
{
    __shared__ float t[32][33];
    int ez = blockIdx.z;
    const float* src = (ez == 0) ? Wc : (We + (size_t)(ez - 1) * Dd * Uu);
    int u0 = blockIdx.x * 32, d0 = blockIdx.y * 32;
    int tx = threadIdx.x, ty = threadIdx.y;
#pragma unroll
    for (int k = 0; k < 32; k += 8)
        t[ty + k][tx] = src[(size_t)(d0 + ty + k) * Uu + u0 + tx];
    __syncthreads();
#pragma unroll
    for (int k = 0; k < 32; k += 8) {
        int u = u0 + ty + k, d = d0 + tx;
        g_wh[(size_t)ez * Uu * Dd + (size_t)u * Dd + d] = __float2half_rn(t[tx][ty + k]);
    }
}

// gate logits: g_logits[b][t][g] = x[b,:] . Wg[t,:,g] + bg[t,g]
__global__ __launch_bounds__(256) void glogits_kernel(
    const float* __restrict__ x, const float* __restrict__ Wg,
    const float* __restrict__ bg)
{
    __shared__ float wgs[Dd * Tt * Gg];   // 40KB
    const int tid = threadIdx.x;
    for (int i = tid; i < Dd * Tt * Gg; i += 256) {
        int d = i / (Tt * Gg), tg = i - d * (Tt * Gg);
        int t = tg / Gg, g = tg - t * Gg;
        wgs[i] = Wg[((size_t)t * Dd + d) * Gg + g];
    }
    __syncthreads();

    const int w = tid >> 5, lane = tid & 31;
    int b = blockIdx.x * 8 + w;
    const float* xr = x + (size_t)b * Dd;
    float acc[Tt * Gg];
#pragma unroll
    for (int j = 0; j < Tt * Gg; j++) acc[j] = 0.f;
    for (int k = lane; k < Dd; k += 32) {
        float xv = xr[k];
        const float* wr = wgs + k * (Tt * Gg);
#pragma unroll
        for (int j = 0; j < Tt * Gg; j++) acc[j] = fmaf(xv, wr[j], acc[j]);
    }
#pragma unroll
    for (int j = 0; j < Tt * Gg; j++) {
#pragma unroll
        for (int o = 16; o; o >>= 1) acc[j] += __shfl_xor_sync(0xffffffffu, acc[j], o);
    }
    if (lane < Tt * Gg) {
        int t = lane / Gg, g = lane - t * Gg;
        g_logits[(size_t)b * (Tt * Gg) + lane] = acc[lane] + bg[t * Gg + g];
    }
}

// ============================================================
// GEMM mainloop: single fp16 pass (R7 structure)
// ============================================================
__device__ __forceinline__ void gemm_mainloop(
    uint32_t sb, const __half* wb, const int* sidx,
    int m0, int n0, int tid, int lane, int wm, int wn,
    float acc[4][8][4])
{
    const int lrow = (lane & 7) + ((lane >> 3) & 1) * 8;
    const int kb   = lane >> 4;

    issue_chunk(sb, 0, wb, sidx, m0, n0, tid);

    for (int ch = 0; ch < NCH; ch++) {
        if (ch + 1 < NCH) {
            issue_chunk(sb, ch + 1, wb, sidx, m0, n0, tid);
            CP_WAIT(1);
        } else {
            CP_WAIT(0);
        }
        __syncthreads();

        uint32_t s0 = sb + (uint32_t)(ch & (NSTG - 1)) * STAGE;
#pragma unroll
        for (int ks = 0; ks < 4; ks++) {
            uint32_t koff = (uint32_t)(ks * 2 + kb) * 16;
            uint32_t af[4][4], bf[4][4];
#pragma unroll
            for (int mi = 0; mi < 4; mi++) {
                uint32_t ro = (uint32_t)(wm + mi * 16 + lrow) * 128 + koff;
                ldsm4(af[mi], s0 + AOF + SWZ(ro));
            }
#pragma unroll
            for (int nj = 0; nj < 4; nj++) {
                uint32_t ro = (uint32_t)(wn + nj * 16 + lrow) * 128 + koff;
                ldsm4(bf[nj], s0 + BOF + SWZ(ro));
            }
#pragma unroll
            for (int mi = 0; mi < 4; mi++)
#pragma unroll
                for (int nj = 0; nj < 4; nj++) {
                    mma16816(acc[mi][2*nj],   af[mi], bf[nj][0], bf[nj][2]);
                    mma16816(acc[mi][2*nj+1], af[mi], bf[nj][1], bf[nj][3]);
                }
        }
        __syncthreads();
    }
}

// ---------------- merged GEMM: z=0 common (dense), z>=1 expert (gathered) ----
__global__ __launch_bounds__(256) void gemm_all(
    const float* __restrict__ bc, const float* __restrict__ be)
{
    extern __shared__ __align__(1024) char dsm[];
    const int z = blockIdx.z;
    const bool dense = (z == 0);
    const int fe = z - 1;
    const int t0 = blockIdx.x * BM;
    int cnt = 0;
    if (!dense) {
        cnt = g_cnt[fe];
        if (t0 >= cnt) return;
    }

    const int tid = threadIdx.x;
    const int w = tid >> 5, lane = tid & 31;
    const int n0 = blockIdx.y * BN;
    const int wm = (w & 1) * 64;
    const int wn = (w >> 1) * 64;
    uint32_t sb = s2u(dsm);
    int* sidx = (int*)(dsm + IDX_OFF);

    if (!dense) {
        if (tid < BM) {
            int s = t0 + tid;
            sidx[tid] = g_idx[fe][(s < cnt) ? s : (cnt - 1)];
        }
        __syncthreads();
    }

    const int ez = dense ? 0 : (1 + fe);
    const __half* wb = g_wh + (size_t)ez * Uu * Dd;

    float acc[4][8][4];
#pragma unroll
    for (int mi = 0; mi < 4; mi++)
#pragma unroll
        for (int ni = 0; ni < 8; ni++)
#pragma unroll
            for (int j = 0; j < 4; j++) acc[mi][ni][j] = 0.f;

    gemm_mainloop(sb, wb, dense ? nullptr : sidx, t0, n0, tid, lane, wm, wn, acc);

    if (dense) {
        const float* bep = bc + n0;
#pragma unroll
        for (int mi = 0; mi < 4; mi++) {
#pragma unroll
            for (int h = 0; h < 2; h++) {
                int rl = wm + mi * 16 + (lane >> 2) + h * 8;
                float* gp = g_common + (size_t)(t0 + rl) * Uu + n0;
#pragma unroll
                for (int ni = 0; ni < 8; ni++) {
                    int cl = wn + ni * 8 + (lane & 3) * 2;
                    float v0 = fmaxf(acc[mi][ni][h * 2 + 0] + bep[cl],     0.f);
                    float v1 = fmaxf(acc[mi][ni][h * 2 + 1] + bep[cl + 1], 0.f);
                    *(float2*)(gp + cl) = make_float2(v0, v1);
                }
            }
        }
    } else {
        const int f = fe >> 2;
        const float* bep = be + (size_t)fe * Uu + n0;
        const bool atom = (f < 2);
#pragma unroll
        for (int mi = 0; mi < 4; mi++) {
#pragma unroll
            for (int h = 0; h < 2; h++) {
                int rl = wm + mi * 16 + (lane >> 2) + h * 8;
                if (t0 + rl >= cnt) continue;
                int grow = sidx[rl];
                float* gp = g_field + (size_t)grow * (Ff * Uu) + (size_t)f * Uu + n0;
#pragma unroll
                for (int ni = 0; ni < 8; ni++) {
                    int cl = wn + ni * 8 + (lane & 3) * 2;
                    float v0 = fmaxf(acc[mi][ni][h * 2 + 0] + bep[cl],     0.f);
                    float v1 = fmaxf(acc[mi][ni][h * 2 + 1] + bep[cl + 1], 0.f);
                    if (atom) {
                        atomicAdd(gp + cl,     v0);
                        atomicAdd(gp + cl + 1, v1);
                    } else {
                        *(float2*)(gp + cl) = make_float2(v0, v1);
                    }
                }
            }
        }
    }
}

// ============================================================
// fused per-row epilogue: att/upd dots + softmax + mix
// ============================================================
__global__ __launch_bounds__(256) void epilogue_kernel(
    const float* __restrict__ Wa, const float* __restrict__ ba,
    const float* __restrict__ Wu, const float* __restrict__ bu,
    float* __restrict__ out)
{
    const int b = blockIdx.x;
    __shared__ float cs[Uu];
    __shared__ float fs[Ff][Uu];
    __shared__ float s_att[Ff], s_upd[Ff];
    __shared__ float s_gates[Tt][Gg];

    const int tid = threadIdx.x;
    for (int i = tid; i < Uu; i += 256)
        cs[i] = g_common[(size_t)b * Uu + i];
    for (int i = tid; i < Ff * Uu; i += 256)
        fs[0][i] = g_field[(size_t)b * Ff * Uu + i];
    __syncthreads();

    const int w = tid >> 5, lane = tid & 31;

    {
        int f = w >> 1;
        const float* Wv = (w & 1) ? (Wu + (size_t)f * 2 * Uu) : (Wa + (size_t)f * 2 * Uu);
        float s = 0.f;
        for (int k = lane; k < Uu; k += 32) s = fmaf(cs[k],    Wv[k],      s);
        for (int k = lane; k < Uu; k += 32) s = fmaf(fs[f][k], Wv[Uu + k], s);
#pragma unroll
        for (int o = 16; o; o >>= 1) s += __shfl_xor_sync(0xffffffffu, s, o);
        if (lane == 0) {
            float bv = (w & 1) ? bu[f] : ba[f];
            float v = 1.f / (1.f + expf(-(s + bv)));
            if (w & 1) s_upd[f] = v; else s_att[f] = v;
        }
    }
    __syncthreads();

    if (tid < Tt) {
        const float* lg = g_logits + (size_t)b * (Tt * Gg) + tid * Gg;
        float mx = lg[0];
#pragma unroll
        for (int g = 1; g < Gg; g++) mx = fmaxf(mx, lg[g]);
        float ex[Gg], sum = 0.f;
#pragma unroll
        for (int g = 0; g < Gg; g++) { ex[g] = expf(lg[g] - mx); sum += ex[g]; }
        float inv = 1.f / sum;
#pragma unroll
        for (int g = 0; g < Gg; g++) s_gates[tid][g] = ex[g] * inv;
    }
    __syncthreads();

    for (int u = tid; u < Uu; u += 256) {
        float c = cs[u];
        float ffv[Ff];
#pragma unroll
        for (int f = 0; f < Ff; f++) {
            float fo = fs[f][u];
            float fa = s_att[f] * fo;
            ffv[f] = s_upd[f] * fa + (1.f - s_upd[f]) * c;
        }
#pragma unroll
        for (int t = 0; t < Tt; t++) {
            float o = s_gates[t][0] * c;
#pragma unroll
            for (int fq = 0; fq < Ff; fq++) o = fmaf(s_gates[t][1 + fq], ffv[fq], o);
            out[((size_t)b * Tt + t) * Uu + u] = o;
        }
    }
}

// ============================================================
// launch
// ============================================================
extern "C" void kernel_launch(void* const* d_in, const int* in_sizes, int n_in,
                              void* d_out, int out_size)
{
    const float* x  = (const float*)d_in[0];
    const float* Wc = (const float*)d_in[1];
    const float* bc = (const float*)d_in[2];
    const float* We = (const float*)d_in[3];
    const float* be = (const float*)d_in[4];
    const float* Wg = (const float*)d_in[5];
    const float* bg = (const float*)d_in[6];
    const float* Wa = (const float*)d_in[7];
    const float* ba = (const float*)d_in[8];
    const float* Wu = (const float*)d_in[9];
    const float* bu = (const float*)d_in[10];
    float* out = (float*)d_out;

    cudaFuncSetAttribute(gemm_all, cudaFuncAttributeMaxDynamicSharedMemorySize, DSM_TOTAL);

    zero_kernel<<<(Bsz * 2 * Uu / 4) / 256, 256>>>();
    build_idx<<<Bsz / 256, 256>>>(x);
    splitx_kernel<<<(Bsz * Dd / 4) / 256, 256>>>(x);
    splitw_kernel<<<dim3(Uu / 32, Dd / 32, NEXP), dim3(32, 8)>>>(Wc, We);
    glogits_kernel<<<Bsz / 8, 256>>>(x, Wg, bg);
    gemm_all<<<dim3(Bsz / BM, Uu / BN, 1 + Ff * Ee), 256, DSM_TOTAL>>>(bc, be);
    epilogue_kernel<<<Bsz, 256>>>(Wa, ba, Wu, bu, out);
}

// round 12
// speedup vs baseline: 2.1582x; 1.0959x over previous
#include <cuda_runtime.h>
#include <cuda_fp16.h>
#include <math.h>
#include <stdint.h>

// ---------------- problem constants ----------------
#define Bsz 8192
#define Dd  1024
#define Uu  512
#define Ff  4
#define Ee  4
#define Tt  2
#define Gg  5
#define NEXP 17

// ---------------- scratch ----------------
__device__ float g_common[Bsz * Uu];
__device__ float g_field [Bsz * Ff * Uu];
__device__ float g_logits[Bsz * Tt * Gg];
__device__ int   g_idx[Ff * Ee][Bsz];
__device__ int   g_cnt[Ff * Ee];
__device__ __half g_xh[Bsz * Dd];                     // fp16 x
__device__ __half g_wh[(size_t)NEXP * Uu * Dd];       // fp16 W, transposed [ez][u][d]

// ---------------- GEMM config (R11-proven; do not touch) ----
#define BM 128
#define BN 256
#define NCH 16
#define AOF 0
#define BOF 16384
#define STAGE 49152
#define NSTG 2
#define IDX_OFF (NSTG * STAGE)
#define DSM_TOTAL (NSTG * STAGE + 1024)

#define SWZ(o) ((o) ^ (((o) >> 3) & 0x70))

__device__ __forceinline__ uint32_t s2u(const void* p) {
    return (uint32_t)__cvta_generic_to_shared(p);
}

__device__ __forceinline__ void cpa16(uint32_t dst, const void* src) {
    asm volatile("cp.async.cg.shared.global [%0], [%1], 16;"
                 :: "r"(dst), "l"(__cvta_generic_to_global(src)));
}
#define CP_COMMIT() asm volatile("cp.async.commit_group;" ::: "memory")
#define CP_WAIT(n)  asm volatile("cp.async.wait_group %0;" :: "n"(n) : "memory")

__device__ __forceinline__ void ldsm4(uint32_t* r, uint32_t addr) {
    asm volatile("ldmatrix.sync.aligned.m8n8.x4.shared.b16 {%0,%1,%2,%3}, [%4];"
                 : "=r"(r[0]), "=r"(r[1]), "=r"(r[2]), "=r"(r[3]) : "r"(addr));
}

__device__ __forceinline__ void mma16816(float* c, const uint32_t* a, uint32_t b0, uint32_t b1) {
    asm volatile(
        "mma.sync.aligned.m16n8k16.row.col.f32.f16.f16.f32 "
        "{%0,%1,%2,%3}, {%4,%5,%6,%7}, {%8,%9}, {%0,%1,%2,%3};"
        : "+f"(c[0]), "+f"(c[1]), "+f"(c[2]), "+f"(c[3])
        : "r"(a[0]), "r"(a[1]), "r"(a[2]), "r"(a[3]), "r"(b0), "r"(b1));
}

// issue one k-chunk (64 k-elems) of cp.async loads into stage ch&1
__device__ __forceinline__ void issue_chunk(uint32_t sb, int ch,
                                            const __half* __restrict__ wb,
                                            const int* __restrict__ sidx,
                                            int m0, int n0, int tid)
{
    uint32_t st = sb + (uint32_t)(ch & (NSTG - 1)) * STAGE;
    const int kbase = ch * 64;
#pragma unroll
    for (int i = 0; i < 4; i++) {
        int u = tid + i * 256, r = u >> 3, cc = u & 7;
        int grow = sidx ? sidx[r] : (m0 + r);
        size_t go = (size_t)grow * Dd + kbase + cc * 8;
        cpa16(st + AOF + SWZ(r * 128 + cc * 16), g_xh + go);
    }
#pragma unroll
    for (int i = 0; i < 8; i++) {
        int u = tid + i * 256, r = u >> 3, cc = u & 7;
        size_t go = (size_t)(n0 + r) * Dd + kbase + cc * 8;
        cpa16(st + BOF + SWZ(r * 128 + cc * 16), wb + go);
    }
    CP_COMMIT();
}

// ============================================================
// prep kernels
// ============================================================
__global__ void zero_cnt()
{
    if (threadIdx.x < Ff * Ee) g_cnt[threadIdx.x] = 0;
}

// one warp per batch row: x->fp16 convert, zero discrete g_field half,
// build active-expert index lists, compute gate logits.
__global__ __launch_bounds__(256) void prep_rows(
    const float* __restrict__ x, const float* __restrict__ Wg,
    const float* __restrict__ bg)
{
    __shared__ float wgs[Dd * Tt * Gg];   // 40KB: Wg as [d][t*5+g]
    const int tid = threadIdx.x;
    for (int i = tid; i < Dd * Tt * Gg; i += 256) {
        int d = i / (Tt * Gg), tg = i - d * (Tt * Gg);
        int t = tg / Gg, g = tg - t * Gg;
        wgs[i] = Wg[((size_t)t * Dd + d) * Gg + g];
    }
    __syncthreads();

    const int w = tid >> 5, lane = tid & 31;
    const int b = blockIdx.x * 8 + w;
    const float* xr = x + (size_t)b * Dd;

    float acc[Tt * Gg];
#pragma unroll
    for (int j = 0; j < Tt * Gg; j++) acc[j] = 0.f;

    // convert + logit accumulate (8 float4 per lane)
#pragma unroll
    for (int j = 0; j < 8; j++) {
        int k4 = lane + j * 32;                  // float4 index in row
        float4 v = ((const float4*)xr)[k4];
        __half2* dst = (__half2*)(g_xh + (size_t)b * Dd + k4 * 4);
        dst[0] = __floats2half2_rn(v.x, v.y);
        dst[1] = __floats2half2_rn(v.z, v.w);
        const float* wr = wgs + (k4 * 4) * (Tt * Gg);
        float vv[4] = {v.x, v.y, v.z, v.w};
#pragma unroll
        for (int q = 0; q < 4; q++)
#pragma unroll
            for (int jj = 0; jj < Tt * Gg; jj++)
                acc[jj] = fmaf(vv[q], wr[q * (Tt * Gg) + jj], acc[jj]);
    }
#pragma unroll
    for (int jj = 0; jj < Tt * Gg; jj++)
#pragma unroll
        for (int o = 16; o; o >>= 1) acc[jj] += __shfl_xor_sync(0xffffffffu, acc[jj], o);
    if (lane < Tt * Gg)
        g_logits[(size_t)b * (Tt * Gg) + lane] = acc[lane] + bg[lane];

    // zero discrete half of g_field row (fields 0,1 = 1024 floats)
    float4* zp = (float4*)(g_field + (size_t)b * (Ff * Uu));
#pragma unroll
    for (int j = 0; j < 8; j++) zp[lane + j * 32] = make_float4(0.f, 0.f, 0.f, 0.f);

    // active-expert index lists
    if (lane < 8) {                                  // discrete: fe == feature idx == lane
        if (xr[lane] > 0.f) {
            int p = atomicAdd(&g_cnt[lane], 1);
            g_idx[lane][p] = b;
        }
    } else if (lane < 10) {                          // continuous fields 2,3
        int f = 2 + (lane - 8);
        float v = xr[8 + (lane - 8)];
        int e = (v <= -0.5f) ? 0 : (v <= 0.f) ? 1 : (v <= 0.5f) ? 2 : 3;
        int fe = f * 4 + e;
        int p = atomicAdd(&g_cnt[fe], 1);
        g_idx[fe][p] = b;
    }
}

__global__ void splitw_kernel(const float* __restrict__ Wc, const float* __restrict__ We)
{
    __shared__ float t[32][33];
    int ez = blockIdx.z;
    const float* src = (ez == 0) ? Wc : (We + (size_t)(ez - 1) * Dd * Uu);
    int u0 = blockIdx.x * 32, d0 = blockIdx.y * 32;
    int tx = threadIdx.x, ty = threadIdx.y;
#pragma unroll
    for (int k = 0; k < 32; k += 8)
        t[ty + k][tx] = src[(size_t)(d0 + ty + k) * Uu + u0 + tx];
    __syncthreads();
#pragma unroll
    for (int k = 0; k < 32; k += 8) {
        int u = u0 + ty + k, d = d0 + tx;
        g_wh[(size_t)ez * Uu * Dd + (size_t)u * Dd + d] = __float2half_rn(t[tx][ty + k]);
    }
}

// ============================================================
// GEMM mainloop: single fp16 pass (R11 structure, unchanged)
// ============================================================
__device__ __forceinline__ void gemm_mainloop(
    uint32_t sb, const __half* wb, const int* sidx,
    int m0, int n0, int tid, int lane, int wm, int wn,
    float acc[4][8][4])
{
    const int lrow = (lane & 7) + ((lane >> 3) & 1) * 8;
    const int kb   = lane >> 4;

    issue_chunk(sb, 0, wb, sidx, m0, n0, tid);

    for (int ch = 0; ch < NCH; ch++) {
        if (ch + 1 < NCH) {
            issue_chunk(sb, ch + 1, wb, sidx, m0, n0, tid);
            CP_WAIT(1);
        } else {
            CP_WAIT(0);
        }
        __syncthreads();

        uint32_t s0 = sb + (uint32_t)(ch & (NSTG - 1)) * STAGE;
#pragma unroll
        for (int ks = 0; ks < 4; ks++) {
            uint32_t koff = (uint32_t)(ks * 2 + kb) * 16;
            uint32_t af[4][4], bf[4][4];
#pragma unroll
            for (int mi = 0; mi < 4; mi++) {
                uint32_t ro = (uint32_t)(wm + mi * 16 + lrow) * 128 + koff;
                ldsm4(af[mi], s0 + AOF + SWZ(ro));
            }
#pragma unroll
            for (int nj = 0; nj < 4; nj++) {
                uint32_t ro = (uint32_t)(wn + nj * 16 + lrow) * 128 + koff;
                ldsm4(bf[nj], s0 + BOF + SWZ(ro));
            }
#pragma unroll
            for (int mi = 0; mi < 4; mi++)
#pragma unroll
                for (int nj = 0; nj < 4; nj++) {
                    mma16816(acc[mi][2*nj],   af[mi], bf[nj][0], bf[nj][2]);
                    mma16816(acc[mi][2*nj+1], af[mi], bf[nj][1], bf[nj][3]);
                }
        }
        __syncthreads();
    }
}

// ---------------- merged GEMM: z=0 common (dense), z>=1 expert (gathered) ----
__global__ __launch_bounds__(256) void gemm_all(
    const float* __restrict__ bc, const float* __restrict__ be)
{
    extern __shared__ __align__(1024) char dsm[];
    const int z = blockIdx.z;
    const bool dense = (z == 0);
    const int fe = z - 1;
    const int t0 = blockIdx.x * BM;
    int cnt = 0;
    if (!dense) {
        cnt = g_cnt[fe];
        if (t0 >= cnt) return;
    }

    const int tid = threadIdx.x;
    const int w = tid >> 5, lane = tid & 31;
    const int n0 = blockIdx.y * BN;
    const int wm = (w & 1) * 64;
    const int wn = (w >> 1) * 64;
    uint32_t sb = s2u(dsm);
    int* sidx = (int*)(dsm + IDX_OFF);

    if (!dense) {
        if (tid < BM) {
            int s = t0 + tid;
            sidx[tid] = g_idx[fe][(s < cnt) ? s : (cnt - 1)];
        }
        __syncthreads();
    }

    const int ez = dense ? 0 : (1 + fe);
    const __half* wb = g_wh + (size_t)ez * Uu * Dd;

    float acc[4][8][4];
#pragma unroll
    for (int mi = 0; mi < 4; mi++)
#pragma unroll
        for (int ni = 0; ni < 8; ni++)
#pragma unroll
            for (int j = 0; j < 4; j++) acc[mi][ni][j] = 0.f;

    gemm_mainloop(sb, wb, dense ? nullptr : sidx, t0, n0, tid, lane, wm, wn, acc);

    if (dense) {
        const float* bep = bc + n0;
#pragma unroll
        for (int mi = 0; mi < 4; mi++) {
#pragma unroll
            for (int h = 0; h < 2; h++) {
                int rl = wm + mi * 16 + (lane >> 2) + h * 8;
                float* gp = g_common + (size_t)(t0 + rl) * Uu + n0;
#pragma unroll
                for (int ni = 0; ni < 8; ni++) {
                    int cl = wn + ni * 8 + (lane & 3) * 2;
                    float v0 = fmaxf(acc[mi][ni][h * 2 + 0] + bep[cl],     0.f);
                    float v1 = fmaxf(acc[mi][ni][h * 2 + 1] + bep[cl + 1], 0.f);
                    *(float2*)(gp + cl) = make_float2(v0, v1);
                }
            }
        }
    } else {
        const int f = fe >> 2;
        const float* bep = be + (size_t)fe * Uu + n0;
        const bool atom = (f < 2);
#pragma unroll
        for (int mi = 0; mi < 4; mi++) {
#pragma unroll
            for (int h = 0; h < 2; h++) {
                int rl = wm + mi * 16 + (lane >> 2) + h * 8;
                if (t0 + rl >= cnt) continue;
                int grow = sidx[rl];
                float* gp = g_field + (size_t)grow * (Ff * Uu) + (size_t)f * Uu + n0;
#pragma unroll
                for (int ni = 0; ni < 8; ni++) {
                    int cl = wn + ni * 8 + (lane & 3) * 2;
                    float v0 = fmaxf(acc[mi][ni][h * 2 + 0] + bep[cl],     0.f);
                    float v1 = fmaxf(acc[mi][ni][h * 2 + 1] + bep[cl + 1], 0.f);
                    if (atom) {
                        atomicAdd(gp + cl,     v0);
                        atomicAdd(gp + cl + 1, v1);
                    } else {
                        *(float2*)(gp + cl) = make_float2(v0, v1);
                    }
                }
            }
        }
    }
}

// ============================================================
// fused per-row epilogue: att/upd dots + softmax + mix
// ============================================================
__global__ __launch_bounds__(256) void epilogue_kernel(
    const float* __restrict__ Wa, const float* __restrict__ ba,
    const float* __restrict__ Wu, const float* __restrict__ bu,
    float* __restrict__ out)
{
    const int b = blockIdx.x;
    __shared__ float cs[Uu];
    __shared__ float fs[Ff][Uu];
    __shared__ float s_att[Ff], s_upd[Ff];
    __shared__ float s_gates[Tt][Gg];

    const int tid = threadIdx.x;
    // vectorized staging
    if (tid < 128)
        ((float4*)cs)[tid] = ((const float4*)(g_common + (size_t)b * Uu))[tid];
    for (int i = tid; i < Ff * Uu / 4; i += 256)
        ((float4*)fs)[i] = ((const float4*)(g_field + (size_t)b * Ff * Uu))[i];
    __syncthreads();

    const int w = tid >> 5, lane = tid & 31;

    {
        int f = w >> 1;
        const float* Wv = (w & 1) ? (Wu + (size_t)f * 2 * Uu) : (Wa + (size_t)f * 2 * Uu);
        float s = 0.f;
        for (int k = lane; k < Uu; k += 32) s = fmaf(cs[k],    Wv[k],      s);
        for (int k = lane; k < Uu; k += 32) s = fmaf(fs[f][k], Wv[Uu + k], s);
#pragma unroll
        for (int o = 16; o; o >>= 1) s += __shfl_xor_sync(0xffffffffu, s, o);
        if (lane == 0) {
            float bv = (w & 1) ? bu[f] : ba[f];
            float v = 1.f / (1.f + expf(-(s + bv)));
            if (w & 1) s_upd[f] = v; else s_att[f] = v;
        }
    }
    __syncthreads();

    if (tid < Tt) {
        const float* lg = g_logits + (size_t)b * (Tt * Gg) + tid * Gg;
        float mx = lg[0];
#pragma unroll
        for (int g = 1; g < Gg; g++) mx = fmaxf(mx, lg[g]);
        float ex[Gg], sum = 0.f;
#pragma unroll
        for (int g = 0; g < Gg; g++) { ex[g] = expf(lg[g] - mx); sum += ex[g]; }
        float inv = 1.f / sum;
#pragma unroll
        for (int g = 0; g < Gg; g++) s_gates[tid][g] = ex[g] * inv;
    }
    __syncthreads();

    for (int u = tid; u < Uu; u += 256) {
        float c = cs[u];
        float ffv[Ff];
#pragma unroll
        for (int f = 0; f < Ff; f++) {
            float fo = fs[f][u];
            float fa = s_att[f] * fo;
            ffv[f] = s_upd[f] * fa + (1.f - s_upd[f]) * c;
        }
#pragma unroll
        for (int t = 0; t < Tt; t++) {
            float o = s_gates[t][0] * c;
#pragma unroll
            for (int fq = 0; fq < Ff; fq++) o = fmaf(s_gates[t][1 + fq], ffv[fq], o);
            out[((size_t)b * Tt + t) * Uu + u] = o;
        }
    }
}

// ============================================================
// launch
// ============================================================
extern "C" void kernel_launch(void* const* d_in, const int* in_sizes, int n_in,
                              void* d_out, int out_size)
{
    const float* x  = (const float*)d_in[0];
    const float* Wc = (const float*)d_in[1];
    const float* bc = (const float*)d_in[2];
    const float* We = (const float*)d_in[3];
    const float* be = (const float*)d_in[4];
    const float* Wg = (const float*)d_in[5];
    const float* bg = (const float*)d_in[6];
    const float* Wa = (const float*)d_in[7];
    const float* ba = (const float*)d_in[8];
    const float* Wu = (const float*)d_in[9];
    const float* bu = (const float*)d_in[10];
    float* out = (float*)d_out;

    cudaFuncSetAttribute(gemm_all, cudaFuncAttributeMaxDynamicSharedMemorySize, DSM_TOTAL);

    zero_cnt<<<1, 32>>>();
    prep_rows<<<Bsz / 8, 256>>>(x, Wg, bg);
    splitw_kernel<<<dim3(Uu / 32, Dd / 32, NEXP), dim3(32, 8)>>>(Wc, We);
    gemm_all<<<dim3(Bsz / BM, Uu / BN, 1 + Ff * Ee), 256, DSM_TOTAL>>>(bc, be);
    epilogue_kernel<<<Bsz, 256>>>(Wa, ba, Wu, bu, out);
}

// round 13
// speedup vs baseline: 2.3875x; 1.1062x over previous
#include <cuda_runtime.h>
#include <cuda_fp16.h>
#include <math.h>
#include <stdint.h>

// ---------------- problem constants ----------------
#define Bsz 8192
#define Dd  1024
#define Uu  512
#define Ff  4
#define Ee  4
#define Tt  2
#define Gg  5
#define NEXP 17

// ---------------- scratch ----------------
__device__ float g_common[Bsz * Uu];
__device__ float g_field [Bsz * Ff * Uu];
__device__ float g_logits[Bsz * Tt * Gg];
__device__ int   g_idx[Ff * Ee][Bsz];
__device__ int   g_cnt[Ff * Ee];
__device__ __half g_xh[Bsz * Dd];                     // fp16 x
__device__ __half g_wh[(size_t)NEXP * Uu * Dd];       // fp16 W, transposed [ez][u][d]

// ---------------- GEMM config: CTA 128x128, 8 warps (64x32 each), 2 CTAs/SM ----
#define BM 128
#define BN 128
#define NCH 16
#define AOF 0
#define BOF 16384
#define STAGE 32768
#define NSTG 2
#define IDX_OFF (NSTG * STAGE)
#define DSM_TOTAL (NSTG * STAGE + 1024)

#define SWZ(o) ((o) ^ (((o) >> 3) & 0x70))

__device__ __forceinline__ uint32_t s2u(const void* p) {
    return (uint32_t)__cvta_generic_to_shared(p);
}

__device__ __forceinline__ void cpa16(uint32_t dst, const void* src) {
    asm volatile("cp.async.cg.shared.global [%0], [%1], 16;"
                 :: "r"(dst), "l"(__cvta_generic_to_global(src)));
}
#define CP_COMMIT() asm volatile("cp.async.commit_group;" ::: "memory")
#define CP_WAIT(n)  asm volatile("cp.async.wait_group %0;" :: "n"(n) : "memory")

__device__ __forceinline__ void ldsm4(uint32_t* r, uint32_t addr) {
    asm volatile("ldmatrix.sync.aligned.m8n8.x4.shared.b16 {%0,%1,%2,%3}, [%4];"
                 : "=r"(r[0]), "=r"(r[1]), "=r"(r[2]), "=r"(r[3]) : "r"(addr));
}

__device__ __forceinline__ void mma16816(float* c, const uint32_t* a, uint32_t b0, uint32_t b1) {
    asm volatile(
        "mma.sync.aligned.m16n8k16.row.col.f32.f16.f16.f32 "
        "{%0,%1,%2,%3}, {%4,%5,%6,%7}, {%8,%9}, {%0,%1,%2,%3};"
        : "+f"(c[0]), "+f"(c[1]), "+f"(c[2]), "+f"(c[3])
        : "r"(a[0]), "r"(a[1]), "r"(a[2]), "r"(a[3]), "r"(b0), "r"(b1));
}

// issue one k-chunk (64 k-elems): A 128x128B + B 128x128B, 8 cp.async/thread
__device__ __forceinline__ void issue_chunk(uint32_t sb, int ch,
                                            const __half* __restrict__ wb,
                                            const int* __restrict__ sidx,
                                            int m0, int n0, int tid)
{
    uint32_t st = sb + (uint32_t)(ch & (NSTG - 1)) * STAGE;
    const int kbase = ch * 64;
#pragma unroll
    for (int i = 0; i < 4; i++) {
        int u = tid + i * 256, r = u >> 3, cc = u & 7;
        int grow = sidx ? sidx[r] : (m0 + r);
        size_t go = (size_t)grow * Dd + kbase + cc * 8;
        cpa16(st + AOF + SWZ(r * 128 + cc * 16), g_xh + go);
    }
#pragma unroll
    for (int i = 0; i < 4; i++) {
        int u = tid + i * 256, r = u >> 3, cc = u & 7;
        size_t go = (size_t)(n0 + r) * Dd + kbase + cc * 8;
        cpa16(st + BOF + SWZ(r * 128 + cc * 16), wb + go);
    }
    CP_COMMIT();
}

// ============================================================
// prep kernels
// ============================================================
__global__ void zero_cnt()
{
    if (threadIdx.x < Ff * Ee) g_cnt[threadIdx.x] = 0;
}

// one warp per batch row: x->fp16, zero discrete g_field half,
// index lists, gate logits.
__global__ __launch_bounds__(256) void prep_rows(
    const float* __restrict__ x, const float* __restrict__ Wg,
    const float* __restrict__ bg)
{
    __shared__ float wgs[Dd * Tt * Gg];   // 40KB: Wg as [d][t*5+g]
    const int tid = threadIdx.x;
    for (int i = tid; i < Dd * Tt * Gg; i += 256) {
        int d = i / (Tt * Gg), tg = i - d * (Tt * Gg);
        int t = tg / Gg, g = tg - t * Gg;
        wgs[i] = Wg[((size_t)t * Dd + d) * Gg + g];
    }
    __syncthreads();

    const int w = tid >> 5, lane = tid & 31;
    const int b = blockIdx.x * 8 + w;
    const float* xr = x + (size_t)b * Dd;

    float acc[Tt * Gg];
#pragma unroll
    for (int j = 0; j < Tt * Gg; j++) acc[j] = 0.f;

#pragma unroll
    for (int j = 0; j < 8; j++) {
        int k4 = lane + j * 32;
        float4 v = ((const float4*)xr)[k4];
        __half2* dst = (__half2*)(g_xh + (size_t)b * Dd + k4 * 4);
        dst[0] = __floats2half2_rn(v.x, v.y);
        dst[1] = __floats2half2_rn(v.z, v.w);
        const float* wr = wgs + (k4 * 4) * (Tt * Gg);
        float vv[4] = {v.x, v.y, v.z, v.w};
#pragma unroll
        for (int q = 0; q < 4; q++)
#pragma unroll
            for (int jj = 0; jj < Tt * Gg; jj++)
                acc[jj] = fmaf(vv[q], wr[q * (Tt * Gg) + jj], acc[jj]);
    }
#pragma unroll
    for (int jj = 0; jj < Tt * Gg; jj++)
#pragma unroll
        for (int o = 16; o; o >>= 1) acc[jj] += __shfl_xor_sync(0xffffffffu, acc[jj], o);
    if (lane < Tt * Gg)
        g_logits[(size_t)b * (Tt * Gg) + lane] = acc[lane] + bg[lane];

    float4* zp = (float4*)(g_field + (size_t)b * (Ff * Uu));
#pragma unroll
    for (int j = 0; j < 8; j++) zp[lane + j * 32] = make_float4(0.f, 0.f, 0.f, 0.f);

    if (lane < 8) {
        if (xr[lane] > 0.f) {
            int p = atomicAdd(&g_cnt[lane], 1);
            g_idx[lane][p] = b;
        }
    } else if (lane < 10) {
        int f = 2 + (lane - 8);
        float v = xr[8 + (lane - 8)];
        int e = (v <= -0.5f) ? 0 : (v <= 0.f) ? 1 : (v <= 0.5f) ? 2 : 3;
        int fe = f * 4 + e;
        int p = atomicAdd(&g_cnt[fe], 1);
        g_idx[fe][p] = b;
    }
}

__global__ void splitw_kernel(const float* __restrict__ Wc, const float* __restrict__ We)
{
    __shared__ float t[32][33];
    int ez = blockIdx.z;
    const float* src = (ez == 0) ? Wc : (We + (size_t)(ez - 1) * Dd * Uu);
    int u0 = blockIdx.x * 32, d0 = blockIdx.y * 32;
    int tx = threadIdx.x, ty = threadIdx.y;
#pragma unroll
    for (int k = 0; k < 32; k += 8)
        t[ty + k][tx] = src[(size_t)(d0 + ty + k) * Uu + u0 + tx];
    __syncthreads();
#pragma unroll
    for (int k = 0; k < 32; k += 8) {
        int u = u0 + ty + k, d = d0 + tx;
        g_wh[(size_t)ez * Uu * Dd + (size_t)u * Dd + d] = __float2half_rn(t[tx][ty + k]);
    }
}

// ============================================================
// GEMM mainloop: single fp16 pass, warp tile 64x32
// ============================================================
__device__ __forceinline__ void gemm_mainloop(
    uint32_t sb, const __half* wb, const int* sidx,
    int m0, int n0, int tid, int lane, int wm, int wn,
    float acc[4][4][4])
{
    const int lrow = (lane & 7) + ((lane >> 3) & 1) * 8;
    const int kb   = lane >> 4;

    issue_chunk(sb, 0, wb, sidx, m0, n0, tid);

    for (int ch = 0; ch < NCH; ch++) {
        if (ch + 1 < NCH) {
            issue_chunk(sb, ch + 1, wb, sidx, m0, n0, tid);
            CP_WAIT(1);
        } else {
            CP_WAIT(0);
        }
        __syncthreads();

        uint32_t s0 = sb + (uint32_t)(ch & (NSTG - 1)) * STAGE;
#pragma unroll
        for (int ks = 0; ks < 4; ks++) {
            uint32_t koff = (uint32_t)(ks * 2 + kb) * 16;
            uint32_t af[4][4], bf[2][4];
#pragma unroll
            for (int mi = 0; mi < 4; mi++) {
                uint32_t ro = (uint32_t)(wm + mi * 16 + lrow) * 128 + koff;
                ldsm4(af[mi], s0 + AOF + SWZ(ro));
            }
#pragma unroll
            for (int nj = 0; nj < 2; nj++) {
                uint32_t ro = (uint32_t)(wn + nj * 16 + lrow) * 128 + koff;
                ldsm4(bf[nj], s0 + BOF + SWZ(ro));
            }
#pragma unroll
            for (int mi = 0; mi < 4; mi++)
#pragma unroll
                for (int nj = 0; nj < 2; nj++) {
                    mma16816(acc[mi][2*nj],   af[mi], bf[nj][0], bf[nj][2]);
                    mma16816(acc[mi][2*nj+1], af[mi], bf[nj][1], bf[nj][3]);
                }
        }
        __syncthreads();
    }
}

// ---------------- merged GEMM: z=0 common (dense), z>=1 expert (gathered) ----
__global__ __launch_bounds__(256, 2) void gemm_all(
    const float* __restrict__ bc, const float* __restrict__ be)
{
    extern __shared__ __align__(1024) char dsm[];
    const int z = blockIdx.z;
    const bool dense = (z == 0);
    const int fe = z - 1;
    const int t0 = blockIdx.x * BM;
    int cnt = 0;
    if (!dense) {
        cnt = g_cnt[fe];
        if (t0 >= cnt) return;
    }

    const int tid = threadIdx.x;
    const int w = tid >> 5, lane = tid & 31;
    const int n0 = blockIdx.y * BN;
    const int wm = (w & 1) * 64;          // 2 m-slots
    const int wn = (w >> 1) * 32;         // 4 n-slots
    uint32_t sb = s2u(dsm);
    int* sidx = (int*)(dsm + IDX_OFF);

    if (!dense) {
        if (tid < BM) {
            int s = t0 + tid;
            sidx[tid] = g_idx[fe][(s < cnt) ? s : (cnt - 1)];
        }
        __syncthreads();
    }

    const int ez = dense ? 0 : (1 + fe);
    const __half* wb = g_wh + (size_t)ez * Uu * Dd;

    float acc[4][4][4];
#pragma unroll
    for (int mi = 0; mi < 4; mi++)
#pragma unroll
        for (int ni = 0; ni < 4; ni++)
#pragma unroll
            for (int j = 0; j < 4; j++) acc[mi][ni][j] = 0.f;

    gemm_mainloop(sb, wb, dense ? nullptr : sidx, t0, n0, tid, lane, wm, wn, acc);

    if (dense) {
        const float* bep = bc + n0;
#pragma unroll
        for (int mi = 0; mi < 4; mi++) {
#pragma unroll
            for (int h = 0; h < 2; h++) {
                int rl = wm + mi * 16 + (lane >> 2) + h * 8;
                float* gp = g_common + (size_t)(t0 + rl) * Uu + n0;
#pragma unroll
                for (int ni = 0; ni < 4; ni++) {
                    int cl = wn + ni * 8 + (lane & 3) * 2;
                    float v0 = fmaxf(acc[mi][ni][h * 2 + 0] + bep[cl],     0.f);
                    float v1 = fmaxf(acc[mi][ni][h * 2 + 1] + bep[cl + 1], 0.f);
                    *(float2*)(gp + cl) = make_float2(v0, v1);
                }
            }
        }
    } else {
        const int f = fe >> 2;
        const float* bep = be + (size_t)fe * Uu + n0;
        const bool atom = (f < 2);
#pragma unroll
        for (int mi = 0; mi < 4; mi++) {
#pragma unroll
            for (int h = 0; h < 2; h++) {
                int rl = wm + mi * 16 + (lane >> 2) + h * 8;
                if (t0 + rl >= cnt) continue;
                int grow = sidx[rl];
                float* gp = g_field + (size_t)grow * (Ff * Uu) + (size_t)f * Uu + n0;
#pragma unroll
                for (int ni = 0; ni < 4; ni++) {
                    int cl = wn + ni * 8 + (lane & 3) * 2;
                    float v0 = fmaxf(acc[mi][ni][h * 2 + 0] + bep[cl],     0.f);
                    float v1 = fmaxf(acc[mi][ni][h * 2 + 1] + bep[cl + 1], 0.f);
                    if (atom) {
                        atomicAdd(gp + cl,     v0);
                        atomicAdd(gp + cl + 1, v1);
                    } else {
                        *(float2*)(gp + cl) = make_float2(v0, v1);
                    }
                }
            }
        }
    }
}

// ============================================================
// fused per-row epilogue: att/upd dots + softmax + mix
// ============================================================
__global__ __launch_bounds__(256) void epilogue_kernel(
    const float* __restrict__ Wa, const float* __restrict__ ba,
    const float* __restrict__ Wu, const float* __restrict__ bu,
    float* __restrict__ out)
{
    const int b = blockIdx.x;
    __shared__ float cs[Uu];
    __shared__ float fs[Ff][Uu];
    __shared__ float s_att[Ff], s_upd[Ff];
    __shared__ float s_gates[Tt][Gg];

    const int tid = threadIdx.x;
    if (tid < 128)
        ((float4*)cs)[tid] = ((const float4*)(g_common + (size_t)b * Uu))[tid];
    for (int i = tid; i < Ff * Uu / 4; i += 256)
        ((float4*)fs)[i] = ((const float4*)(g_field + (size_t)b * Ff * Uu))[i];
    __syncthreads();

    const int w = tid >> 5, lane = tid & 31;

    {
        int f = w >> 1;
        const float* Wv = (w & 1) ? (Wu + (size_t)f * 2 * Uu) : (Wa + (size_t)f * 2 * Uu);
        float s = 0.f;
        for (int k = lane; k < Uu; k += 32) s = fmaf(cs[k],    Wv[k],      s);
        for (int k = lane; k < Uu; k += 32) s = fmaf(fs[f][k], Wv[Uu + k], s);
#pragma unroll
        for (int o = 16; o; o >>= 1) s += __shfl_xor_sync(0xffffffffu, s, o);
        if (lane == 0) {
            float bv = (w & 1) ? bu[f] : ba[f];
            float v = 1.f / (1.f + expf(-(s + bv)));
            if (w & 1) s_upd[f] = v; else s_att[f] = v;
        }
    }
    __syncthreads();

    if (tid < Tt) {
        const float* lg = g_logits + (size_t)b * (Tt * Gg) + tid * Gg;
        float mx = lg[0];
#pragma unroll
        for (int g = 1; g < Gg; g++) mx = fmaxf(mx, lg[g]);
        float ex[Gg], sum = 0.f;
#pragma unroll
        for (int g = 0; g < Gg; g++) { ex[g] = expf(lg[g] - mx); sum += ex[g]; }
        float inv = 1.f / sum;
#pragma unroll
        for (int g = 0; g < Gg; g++) s_gates[tid][g] = ex[g] * inv;
    }
    __syncthreads();

    for (int u = tid; u < Uu; u += 256) {
        float c = cs[u];
        float ffv[Ff];
#pragma unroll
        for (int f = 0; f < Ff; f++) {
            float fo = fs[f][u];
            float fa = s_att[f] * fo;
            ffv[f] = s_upd[f] * fa + (1.f - s_upd[f]) * c;
        }
#pragma unroll
        for (int t = 0; t < Tt; t++) {
            float o = s_gates[t][0] * c;
#pragma unroll
            for (int fq = 0; fq < Ff; fq++) o = fmaf(s_gates[t][1 + fq], ffv[fq], o);
            out[((size_t)b * Tt + t) * Uu + u] = o;
        }
    }
}

// ============================================================
// launch
// ============================================================
extern "C" void kernel_launch(void* const* d_in, const int* in_sizes, int n_in,
                              void* d_out, int out_size)
{
    const float* x  = (const float*)d_in[0];
    const float* Wc = (const float*)d_in[1];
    const float* bc = (const float*)d_in[2];
    const float* We = (const float*)d_in[3];
    const float* be = (const float*)d_in[4];
    const float* Wg = (const float*)d_in[5];
    const float* bg = (const float*)d_in[6];
    const float* Wa = (const float*)d_in[7];
    const float* ba = (const float*)d_in[8];
    const float* Wu = (const float*)d_in[9];
    const float* bu = (const float*)d_in[10];
    float* out = (float*)d_out;

    cudaFuncSetAttribute(gemm_all, cudaFuncAttributeMaxDynamicSharedMemorySize, DSM_TOTAL);

    zero_cnt<<<1, 32>>>();
    prep_rows<<<Bsz / 8, 256>>>(x, Wg, bg);
    splitw_kernel<<<dim3(Uu / 32, Dd / 32, NEXP), dim3(32, 8)>>>(Wc, We);
    gemm_all<<<dim3(Bsz / BM, Uu / BN, 1 + Ff * Ee), 256, DSM_TOTAL>>>(bc, be);
    epilogue_kernel<<<Bsz, 256>>>(Wa, ba, Wu, bu, out);
}

// round 14
// speedup vs baseline: 2.5652x; 1.0744x over previous
#include <cuda_runtime.h>
#include <cuda_fp16.h>
#include <math.h>
#include <stdint.h>

// ---------------- problem constants ----------------
#define Bsz 8192
#define Dd  1024
#define Uu  512
#define Ff  4
#define Ee  4
#define Tt  2
#define Gg  5
#define NEXP 17

// ---------------- scratch ----------------
__device__ __half g_common[Bsz * Uu];                 // fp16 intermediates
__device__ __half g_field [Bsz * Ff * Uu];
__device__ float  g_logits[Bsz * Tt * Gg];
__device__ int    g_idx[Ff * Ee][Bsz];
__device__ int    g_cnt[Ff * Ee];
__device__ __half g_xh[Bsz * Dd];                     // fp16 x
__device__ __half g_wh[(size_t)NEXP * Uu * Dd];       // fp16 W, transposed [ez][u][d]

// ---------------- GEMM config: CTA 128x128, 8 warps (64x32), 2 CTAs/SM ----
#define BM 128
#define BN 128
#define NCH 16
#define AOF 0
#define BOF 16384
#define STAGE 32768
#define NSTG 2
#define IDX_OFF (NSTG * STAGE)
#define DSM_TOTAL (NSTG * STAGE + 1024)

#define SWZ(o) ((o) ^ (((o) >> 3) & 0x70))

__device__ __forceinline__ uint32_t s2u(const void* p) {
    return (uint32_t)__cvta_generic_to_shared(p);
}

__device__ __forceinline__ void cpa16(uint32_t dst, const void* src) {
    asm volatile("cp.async.cg.shared.global [%0], [%1], 16;"
                 :: "r"(dst), "l"(__cvta_generic_to_global(src)));
}
#define CP_COMMIT() asm volatile("cp.async.commit_group;" ::: "memory")
#define CP_WAIT(n)  asm volatile("cp.async.wait_group %0;" :: "n"(n) : "memory")

__device__ __forceinline__ void ldsm4(uint32_t* r, uint32_t addr) {
    asm volatile("ldmatrix.sync.aligned.m8n8.x4.shared.b16 {%0,%1,%2,%3}, [%4];"
                 : "=r"(r[0]), "=r"(r[1]), "=r"(r[2]), "=r"(r[3]) : "r"(addr));
}

__device__ __forceinline__ void mma16816(float* c, const uint32_t* a, uint32_t b0, uint32_t b1) {
    asm volatile(
        "mma.sync.aligned.m16n8k16.row.col.f32.f16.f16.f32 "
        "{%0,%1,%2,%3}, {%4,%5,%6,%7}, {%8,%9}, {%0,%1,%2,%3};"
        : "+f"(c[0]), "+f"(c[1]), "+f"(c[2]), "+f"(c[3])
        : "r"(a[0]), "r"(a[1]), "r"(a[2]), "r"(a[3]), "r"(b0), "r"(b1));
}

// issue one k-chunk (64 k-elems): A 128x128B + B 128x128B
__device__ __forceinline__ void issue_chunk(uint32_t sb, int ch,
                                            const __half* __restrict__ wb,
                                            const int* __restrict__ sidx,
                                            int m0, int n0, int tid)
{
    uint32_t st = sb + (uint32_t)(ch & (NSTG - 1)) * STAGE;
    const int kbase = ch * 64;
#pragma unroll
    for (int i = 0; i < 4; i++) {
        int u = tid + i * 256, r = u >> 3, cc = u & 7;
        int grow = sidx ? sidx[r] : (m0 + r);
        size_t go = (size_t)grow * Dd + kbase + cc * 8;
        cpa16(st + AOF + SWZ(r * 128 + cc * 16), g_xh + go);
    }
#pragma unroll
    for (int i = 0; i < 4; i++) {
        int u = tid + i * 256, r = u >> 3, cc = u & 7;
        size_t go = (size_t)(n0 + r) * Dd + kbase + cc * 8;
        cpa16(st + BOF + SWZ(r * 128 + cc * 16), wb + go);
    }
    CP_COMMIT();
}

// ============================================================
// prep
// ============================================================
__global__ void zero_cnt()
{
    if (threadIdx.x < Ff * Ee) g_cnt[threadIdx.x] = 0;
}

#define PREP_BLOCKS (Bsz / 8)                 // 1024
#define SPLITW_BLOCKS (16 * 32 * NEXP)        // 8704

// merged prep: blocks [0,1024) do per-row prep; rest transpose+convert W
__global__ __launch_bounds__(256) void prep_merged(
    const float* __restrict__ x, const float* __restrict__ Wg,
    const float* __restrict__ bg,
    const float* __restrict__ Wc, const float* __restrict__ We)
{
    __shared__ float smem_f[Dd * Tt * Gg];    // 40KB (prep); splitw uses first 4.3KB
    const int tid = threadIdx.x;

    if (blockIdx.x < PREP_BLOCKS) {
        // ---- per-row prep: x->fp16, logits, zero discrete field half, idx lists
        float* wgs = smem_f;
        for (int i = tid; i < Dd * Tt * Gg; i += 256) {
            int d = i / (Tt * Gg), tg = i - d * (Tt * Gg);
            int t = tg / Gg, g = tg - t * Gg;
            wgs[i] = Wg[((size_t)t * Dd + d) * Gg + g];
        }
        __syncthreads();

        const int w = tid >> 5, lane = tid & 31;
        const int b = blockIdx.x * 8 + w;
        const float* xr = x + (size_t)b * Dd;

        float acc[Tt * Gg];
#pragma unroll
        for (int j = 0; j < Tt * Gg; j++) acc[j] = 0.f;

#pragma unroll
        for (int j = 0; j < 8; j++) {
            int k4 = lane + j * 32;
            float4 v = ((const float4*)xr)[k4];
            __half2* dst = (__half2*)(g_xh + (size_t)b * Dd + k4 * 4);
            dst[0] = __floats2half2_rn(v.x, v.y);
            dst[1] = __floats2half2_rn(v.z, v.w);
            const float* wr = wgs + (k4 * 4) * (Tt * Gg);
            float vv[4] = {v.x, v.y, v.z, v.w};
#pragma unroll
            for (int q = 0; q < 4; q++)
#pragma unroll
                for (int jj = 0; jj < Tt * Gg; jj++)
                    acc[jj] = fmaf(vv[q], wr[q * (Tt * Gg) + jj], acc[jj]);
        }
#pragma unroll
        for (int jj = 0; jj < Tt * Gg; jj++)
#pragma unroll
            for (int o = 16; o; o >>= 1) acc[jj] += __shfl_xor_sync(0xffffffffu, acc[jj], o);
        if (lane < Tt * Gg)
            g_logits[(size_t)b * (Tt * Gg) + lane] = acc[lane] + bg[lane];

        // zero discrete half (fields 0,1): 1024 halves = 2KB = 128 uint4
        uint4* zp = (uint4*)(g_field + (size_t)b * (Ff * Uu));
#pragma unroll
        for (int j = 0; j < 4; j++) zp[lane + j * 32] = make_uint4(0u, 0u, 0u, 0u);

        if (lane < 8) {
            if (xr[lane] > 0.f) {
                int p = atomicAdd(&g_cnt[lane], 1);
                g_idx[lane][p] = b;
            }
        } else if (lane < 10) {
            int f = 2 + (lane - 8);
            float v = xr[8 + (lane - 8)];
            int e = (v <= -0.5f) ? 0 : (v <= 0.f) ? 1 : (v <= 0.5f) ? 2 : 3;
            int fe = f * 4 + e;
            int p = atomicAdd(&g_cnt[fe], 1);
            g_idx[fe][p] = b;
        }
    } else {
        // ---- splitw: transpose [D,U]->[U,D] + fp16 convert, 32x32 tile
        float (*t)[33] = (float(*)[33])smem_f;
        int i = blockIdx.x - PREP_BLOCKS;
        int ez = i >> 9;                      // / 512
        int rem = i & 511;
        int u0 = (rem & 15) * 32;
        int d0 = (rem >> 4) * 32;
        const float* src = (ez == 0) ? Wc : (We + (size_t)(ez - 1) * Dd * Uu);
        int tx = tid & 31, ty = tid >> 5;     // 32 x 8
#pragma unroll
        for (int k = 0; k < 32; k += 8)
            t[ty + k][tx] = src[(size_t)(d0 + ty + k) * Uu + u0 + tx];
        __syncthreads();
#pragma unroll
        for (int k = 0; k < 32; k += 8) {
            int u = u0 + ty + k, d = d0 + tx;
            g_wh[(size_t)ez * Uu * Dd + (size_t)u * Dd + d] = __float2half_rn(t[tx][ty + k]);
        }
    }
}

// ============================================================
// GEMM mainloop: single fp16 pass, warp tile 64x32 (R13, frozen)
// ============================================================
__device__ __forceinline__ void gemm_mainloop(
    uint32_t sb, const __half* wb, const int* sidx,
    int m0, int n0, int tid, int lane, int wm, int wn,
    float acc[4][4][4])
{
    const int lrow = (lane & 7) + ((lane >> 3) & 1) * 8;
    const int kb   = lane >> 4;

    issue_chunk(sb, 0, wb, sidx, m0, n0, tid);

    for (int ch = 0; ch < NCH; ch++) {
        if (ch + 1 < NCH) {
            issue_chunk(sb, ch + 1, wb, sidx, m0, n0, tid);
            CP_WAIT(1);
        } else {
            CP_WAIT(0);
        }
        __syncthreads();

        uint32_t s0 = sb + (uint32_t)(ch & (NSTG - 1)) * STAGE;
#pragma unroll
        for (int ks = 0; ks < 4; ks++) {
            uint32_t koff = (uint32_t)(ks * 2 + kb) * 16;
            uint32_t af[4][4], bf[2][4];
#pragma unroll
            for (int mi = 0; mi < 4; mi++) {
                uint32_t ro = (uint32_t)(wm + mi * 16 + lrow) * 128 + koff;
                ldsm4(af[mi], s0 + AOF + SWZ(ro));
            }
#pragma unroll
            for (int nj = 0; nj < 2; nj++) {
                uint32_t ro = (uint32_t)(wn + nj * 16 + lrow) * 128 + koff;
                ldsm4(bf[nj], s0 + BOF + SWZ(ro));
            }
#pragma unroll
            for (int mi = 0; mi < 4; mi++)
#pragma unroll
                for (int nj = 0; nj < 2; nj++) {
                    mma16816(acc[mi][2*nj],   af[mi], bf[nj][0], bf[nj][2]);
                    mma16816(acc[mi][2*nj+1], af[mi], bf[nj][1], bf[nj][3]);
                }
        }
        __syncthreads();
    }
}

// ---------------- merged GEMM: z=0 common (dense), z>=1 expert (gathered) ----
__global__ __launch_bounds__(256, 2) void gemm_all(
    const float* __restrict__ bc, const float* __restrict__ be)
{
    extern __shared__ __align__(1024) char dsm[];
    const int z = blockIdx.z;
    const bool dense = (z == 0);
    const int fe = z - 1;
    const int t0 = blockIdx.x * BM;
    int cnt = 0;
    if (!dense) {
        cnt = g_cnt[fe];
        if (t0 >= cnt) return;
    }

    const int tid = threadIdx.x;
    const int w = tid >> 5, lane = tid & 31;
    const int n0 = blockIdx.y * BN;
    const int wm = (w & 1) * 64;
    const int wn = (w >> 1) * 32;
    uint32_t sb = s2u(dsm);
    int* sidx = (int*)(dsm + IDX_OFF);

    if (!dense) {
        if (tid < BM) {
            int s = t0 + tid;
            sidx[tid] = g_idx[fe][(s < cnt) ? s : (cnt - 1)];
        }
        __syncthreads();
    }

    const int ez = dense ? 0 : (1 + fe);
    const __half* wb = g_wh + (size_t)ez * Uu * Dd;

    float acc[4][4][4];
#pragma unroll
    for (int mi = 0; mi < 4; mi++)
#pragma unroll
        for (int ni = 0; ni < 4; ni++)
#pragma unroll
            for (int j = 0; j < 4; j++) acc[mi][ni][j] = 0.f;

    gemm_mainloop(sb, wb, dense ? nullptr : sidx, t0, n0, tid, lane, wm, wn, acc);

    if (dense) {
        const float* bep = bc + n0;
#pragma unroll
        for (int mi = 0; mi < 4; mi++) {
#pragma unroll
            for (int h = 0; h < 2; h++) {
                int rl = wm + mi * 16 + (lane >> 2) + h * 8;
                __half* gp = g_common + (size_t)(t0 + rl) * Uu + n0;
#pragma unroll
                for (int ni = 0; ni < 4; ni++) {
                    int cl = wn + ni * 8 + (lane & 3) * 2;
                    float v0 = fmaxf(acc[mi][ni][h * 2 + 0] + bep[cl],     0.f);
                    float v1 = fmaxf(acc[mi][ni][h * 2 + 1] + bep[cl + 1], 0.f);
                    *(__half2*)(gp + cl) = __floats2half2_rn(v0, v1);
                }
            }
        }
    } else {
        const int f = fe >> 2;
        const float* bep = be + (size_t)fe * Uu + n0;
        const bool atom = (f < 2);
#pragma unroll
        for (int mi = 0; mi < 4; mi++) {
#pragma unroll
            for (int h = 0; h < 2; h++) {
                int rl = wm + mi * 16 + (lane >> 2) + h * 8;
                if (t0 + rl >= cnt) continue;
                int grow = sidx[rl];
                __half* gp = g_field + (size_t)grow * (Ff * Uu) + (size_t)f * Uu + n0;
#pragma unroll
                for (int ni = 0; ni < 4; ni++) {
                    int cl = wn + ni * 8 + (lane & 3) * 2;
                    float v0 = fmaxf(acc[mi][ni][h * 2 + 0] + bep[cl],     0.f);
                    float v1 = fmaxf(acc[mi][ni][h * 2 + 1] + bep[cl + 1], 0.f);
                    __half2 hv = __floats2half2_rn(v0, v1);
                    if (atom) atomicAdd((__half2*)(gp + cl), hv);
                    else      *(__half2*)(gp + cl) = hv;
                }
            }
        }
    }
}

// ============================================================
// fused per-row epilogue: att/upd dots + softmax + mix
// ============================================================
__global__ __launch_bounds__(256) void epilogue_kernel(
    const float* __restrict__ Wa, const float* __restrict__ ba,
    const float* __restrict__ Wu, const float* __restrict__ bu,
    float* __restrict__ out)
{
    const int b = blockIdx.x;
    __shared__ float cs[Uu];
    __shared__ float fs[Ff][Uu];
    __shared__ float s_att[Ff], s_upd[Ff];
    __shared__ float s_gates[Tt][Gg];

    const int tid = threadIdx.x;
    // stage fp16 intermediates -> float smem
    if (tid < 64) {                                   // 512 halves = 64 uint4
        uint4 p = ((const uint4*)(g_common + (size_t)b * Uu))[tid];
        const __half2* h = (const __half2*)&p;
        float2* cd = (float2*)(cs + tid * 8);
#pragma unroll
        for (int q = 0; q < 4; q++) cd[q] = __half22float2(h[q]);
    }
    {                                                 // 2048 halves = 256 uint4
        uint4 p = ((const uint4*)(g_field + (size_t)b * Ff * Uu))[tid];
        const __half2* h = (const __half2*)&p;
        float2* fd = (float2*)(&fs[0][0] + tid * 8);
#pragma unroll
        for (int q = 0; q < 4; q++) fd[q] = __half22float2(h[q]);
    }
    __syncthreads();

    const int w = tid >> 5, lane = tid & 31;

    {
        int f = w >> 1;
        const float* Wv = (w & 1) ? (Wu + (size_t)f * 2 * Uu) : (Wa + (size_t)f * 2 * Uu);
        float s = 0.f;
        for (int k = lane; k < Uu; k += 32) s = fmaf(cs[k],    Wv[k],      s);
        for (int k = lane; k < Uu; k += 32) s = fmaf(fs[f][k], Wv[Uu + k], s);
#pragma unroll
        for (int o = 16; o; o >>= 1) s += __shfl_xor_sync(0xffffffffu, s, o);
        if (lane == 0) {
            float bv = (w & 1) ? bu[f] : ba[f];
            float v = 1.f / (1.f + expf(-(s + bv)));
            if (w & 1) s_upd[f] = v; else s_att[f] = v;
        }
    }
    __syncthreads();

    if (tid < Tt) {
        const float* lg = g_logits + (size_t)b * (Tt * Gg) + tid * Gg;
        float mx = lg[0];
#pragma unroll
        for (int g = 1; g < Gg; g++) mx = fmaxf(mx, lg[g]);
        float ex[Gg], sum = 0.f;
#pragma unroll
        for (int g = 0; g < Gg; g++) { ex[g] = expf(lg[g] - mx); sum += ex[g]; }
        float inv = 1.f / sum;
#pragma unroll
        for (int g = 0; g < Gg; g++) s_gates[tid][g] = ex[g] * inv;
    }
    __syncthreads();

    for (int u = tid; u < Uu; u += 256) {
        float c = cs[u];
        float ffv[Ff];
#pragma unroll
        for (int f = 0; f < Ff; f++) {
            float fo = fs[f][u];
            float fa = s_att[f] * fo;
            ffv[f] = s_upd[f] * fa + (1.f - s_upd[f]) * c;
        }
#pragma unroll
        for (int t = 0; t < Tt; t++) {
            float o = s_gates[t][0] * c;
#pragma unroll
            for (int fq = 0; fq < Ff; fq++) o = fmaf(s_gates[t][1 + fq], ffv[fq], o);
            out[((size_t)b * Tt + t) * Uu + u] = o;
        }
    }
}

// ============================================================
// launch
// ============================================================
extern "C" void kernel_launch(void* const* d_in, const int* in_sizes, int n_in,
                              void* d_out, int out_size)
{
    const float* x  = (const float*)d_in[0];
    const float* Wc = (const float*)d_in[1];
    const float* bc = (const float*)d_in[2];
    const float* We = (const float*)d_in[3];
    const float* be = (const float*)d_in[4];
    const float* Wg = (const float*)d_in[5];
    const float* bg = (const float*)d_in[6];
    const float* Wa = (const float*)d_in[7];
    const float* ba = (const float*)d_in[8];
    const float* Wu = (const float*)d_in[9];
    const float* bu = (const float*)d_in[10];
    float* out = (float*)d_out;

    cudaFuncSetAttribute(gemm_all, cudaFuncAttributeMaxDynamicSharedMemorySize, DSM_TOTAL);

    zero_cnt<<<1, 32>>>();
    prep_merged<<<PREP_BLOCKS + SPLITW_BLOCKS, 256>>>(x, Wg, bg, Wc, We);
    gemm_all<<<dim3(Bsz / BM, Uu / BN, 1 + Ff * Ee), 256, DSM_TOTAL>>>(bc, be);
    epilogue_kernel<<<Bsz, 256>>>(Wa, ba, Wu, bu, out);
}

// round 15
// speedup vs baseline: 2.6378x; 1.0283x over previous
#include <cuda_runtime.h>
#include <cuda_fp16.h>
#include <math.h>
#include <stdint.h>

// ---------------- problem constants ----------------
#define Bsz 8192
#define Dd  1024
#define Uu  512
#define Ff  4
#define Ee  4
#define Tt  2
#define Gg  5
#define NEXP 17

// ---------------- scratch ----------------
__device__ __half g_common[Bsz * Uu];                 // fp16 intermediates
__device__ __half g_field [Bsz * Ff * Uu];
__device__ float  g_logits[Bsz * Tt * Gg];
__device__ int    g_idx[Ff * Ee][Bsz];
__device__ int    g_cnt[Ff * Ee];
__device__ __half g_xh[Bsz * Dd];                     // fp16 x
__device__ __half g_wh[(size_t)NEXP * Uu * Dd];       // fp16 W, transposed [ez][u][d]

// ---------------- GEMM config: CTA 128x128, 8 warps (64x32), 2 CTAs/SM ----
#define BM 128
#define BN 128
#define NCH 16
#define AOF 0
#define BOF 16384
#define STAGE 32768
#define NSTG 2
#define IDX_OFF (NSTG * STAGE)
#define DSM_TOTAL (NSTG * STAGE + 1024)

#define SWZ(o) ((o) ^ (((o) >> 3) & 0x70))

__device__ __forceinline__ uint32_t s2u(const void* p) {
    return (uint32_t)__cvta_generic_to_shared(p);
}

__device__ __forceinline__ void cpa16(uint32_t dst, const void* src) {
    asm volatile("cp.async.cg.shared.global [%0], [%1], 16;"
                 :: "r"(dst), "l"(__cvta_generic_to_global(src)));
}
#define CP_COMMIT() asm volatile("cp.async.commit_group;" ::: "memory")
#define CP_WAIT(n)  asm volatile("cp.async.wait_group %0;" :: "n"(n) : "memory")

__device__ __forceinline__ void ldsm4(uint32_t* r, uint32_t addr) {
    asm volatile("ldmatrix.sync.aligned.m8n8.x4.shared.b16 {%0,%1,%2,%3}, [%4];"
                 : "=r"(r[0]), "=r"(r[1]), "=r"(r[2]), "=r"(r[3]) : "r"(addr));
}

__device__ __forceinline__ void mma16816(float* c, const uint32_t* a, uint32_t b0, uint32_t b1) {
    asm volatile(
        "mma.sync.aligned.m16n8k16.row.col.f32.f16.f16.f32 "
        "{%0,%1,%2,%3}, {%4,%5,%6,%7}, {%8,%9}, {%0,%1,%2,%3};"
        : "+f"(c[0]), "+f"(c[1]), "+f"(c[2]), "+f"(c[3])
        : "r"(a[0]), "r"(a[1]), "r"(a[2]), "r"(a[3]), "r"(b0), "r"(b1));
}

// issue one k-chunk (64 k-elems): A 128x128B + B 128x128B
__device__ __forceinline__ void issue_chunk(uint32_t sb, int ch,
                                            const __half* __restrict__ wb,
                                            const int* __restrict__ sidx,
                                            int m0, int n0, int tid)
{
    uint32_t st = sb + (uint32_t)(ch & (NSTG - 1)) * STAGE;
    const int kbase = ch * 64;
#pragma unroll
    for (int i = 0; i < 4; i++) {
        int u = tid + i * 256, r = u >> 3, cc = u & 7;
        int grow = sidx ? sidx[r] : (m0 + r);
        size_t go = (size_t)grow * Dd + kbase + cc * 8;
        cpa16(st + AOF + SWZ(r * 128 + cc * 16), g_xh + go);
    }
#pragma unroll
    for (int i = 0; i < 4; i++) {
        int u = tid + i * 256, r = u >> 3, cc = u & 7;
        size_t go = (size_t)(n0 + r) * Dd + kbase + cc * 8;
        cpa16(st + BOF + SWZ(r * 128 + cc * 16), wb + go);
    }
    CP_COMMIT();
}

// ============================================================
// prep
// ============================================================
__global__ void zero_cnt()
{
    if (threadIdx.x < Ff * Ee) g_cnt[threadIdx.x] = 0;
}

#define PREP_BLOCKS (Bsz / 8)                 // 1024
#define SPLITW_BLOCKS (16 * 32 * NEXP)        // 8704

// merged prep: blocks [0,1024) per-row prep; rest transpose+convert W
__global__ __launch_bounds__(256) void prep_merged(
    const float* __restrict__ x, const float* __restrict__ Wg,
    const float* __restrict__ bg,
    const float* __restrict__ Wc, const float* __restrict__ We)
{
    __shared__ float smem_f[Dd * Tt * Gg];
    const int tid = threadIdx.x;

    if (blockIdx.x < PREP_BLOCKS) {
        float* wgs = smem_f;
        for (int i = tid; i < Dd * Tt * Gg; i += 256) {
            int d = i / (Tt * Gg), tg = i - d * (Tt * Gg);
            int t = tg / Gg, g = tg - t * Gg;
            wgs[i] = Wg[((size_t)t * Dd + d) * Gg + g];
        }
        __syncthreads();

        const int w = tid >> 5, lane = tid & 31;
        const int b = blockIdx.x * 8 + w;
        const float* xr = x + (size_t)b * Dd;

        float acc[Tt * Gg];
#pragma unroll
        for (int j = 0; j < Tt * Gg; j++) acc[j] = 0.f;

#pragma unroll
        for (int j = 0; j < 8; j++) {
            int k4 = lane + j * 32;
            float4 v = ((const float4*)xr)[k4];
            __half2* dst = (__half2*)(g_xh + (size_t)b * Dd + k4 * 4);
            dst[0] = __floats2half2_rn(v.x, v.y);
            dst[1] = __floats2half2_rn(v.z, v.w);
            const float* wr = wgs + (k4 * 4) * (Tt * Gg);
            float vv[4] = {v.x, v.y, v.z, v.w};
#pragma unroll
            for (int q = 0; q < 4; q++)
#pragma unroll
                for (int jj = 0; jj < Tt * Gg; jj++)
                    acc[jj] = fmaf(vv[q], wr[q * (Tt * Gg) + jj], acc[jj]);
        }
#pragma unroll
        for (int jj = 0; jj < Tt * Gg; jj++)
#pragma unroll
            for (int o = 16; o; o >>= 1) acc[jj] += __shfl_xor_sync(0xffffffffu, acc[jj], o);
        if (lane < Tt * Gg)
            g_logits[(size_t)b * (Tt * Gg) + lane] = acc[lane] + bg[lane];

        uint4* zp = (uint4*)(g_field + (size_t)b * (Ff * Uu));
#pragma unroll
        for (int j = 0; j < 4; j++) zp[lane + j * 32] = make_uint4(0u, 0u, 0u, 0u);

        if (lane < 8) {
            if (xr[lane] > 0.f) {
                int p = atomicAdd(&g_cnt[lane], 1);
                g_idx[lane][p] = b;
            }
        } else if (lane < 10) {
            int f = 2 + (lane - 8);
            float v = xr[8 + (lane - 8)];
            int e = (v <= -0.5f) ? 0 : (v <= 0.f) ? 1 : (v <= 0.5f) ? 2 : 3;
            int fe = f * 4 + e;
            int p = atomicAdd(&g_cnt[fe], 1);
            g_idx[fe][p] = b;
        }
    } else {
        float (*t)[33] = (float(*)[33])smem_f;
        int i = blockIdx.x - PREP_BLOCKS;
        int ez = i >> 9;
        int rem = i & 511;
        int u0 = (rem & 15) * 32;
        int d0 = (rem >> 4) * 32;
        const float* src = (ez == 0) ? Wc : (We + (size_t)(ez - 1) * Dd * Uu);
        int tx = tid & 31, ty = tid >> 5;
#pragma unroll
        for (int k = 0; k < 32; k += 8)
            t[ty + k][tx] = src[(size_t)(d0 + ty + k) * Uu + u0 + tx];
        __syncthreads();
#pragma unroll
        for (int k = 0; k < 32; k += 8) {
            int u = u0 + ty + k, d = d0 + tx;
            g_wh[(size_t)ez * Uu * Dd + (size_t)u * Dd + d] = __float2half_rn(t[tx][ty + k]);
        }
    }
}

// ============================================================
// GEMM mainloop: single fp16 pass, warp tile 64x32 (frozen)
// ============================================================
__device__ __forceinline__ void gemm_mainloop(
    uint32_t sb, const __half* wb, const int* sidx,
    int m0, int n0, int tid, int lane, int wm, int wn,
    float acc[4][4][4])
{
    const int lrow = (lane & 7) + ((lane >> 3) & 1) * 8;
    const int kb   = lane >> 4;

    issue_chunk(sb, 0, wb, sidx, m0, n0, tid);

    for (int ch = 0; ch < NCH; ch++) {
        if (ch + 1 < NCH) {
            issue_chunk(sb, ch + 1, wb, sidx, m0, n0, tid);
            CP_WAIT(1);
        } else {
            CP_WAIT(0);
        }
        __syncthreads();

        uint32_t s0 = sb + (uint32_t)(ch & (NSTG - 1)) * STAGE;
#pragma unroll
        for (int ks = 0; ks < 4; ks++) {
            uint32_t koff = (uint32_t)(ks * 2 + kb) * 16;
            uint32_t af[4][4], bf[2][4];
#pragma unroll
            for (int mi = 0; mi < 4; mi++) {
                uint32_t ro = (uint32_t)(wm + mi * 16 + lrow) * 128 + koff;
                ldsm4(af[mi], s0 + AOF + SWZ(ro));
            }
#pragma unroll
            for (int nj = 0; nj < 2; nj++) {
                uint32_t ro = (uint32_t)(wn + nj * 16 + lrow) * 128 + koff;
                ldsm4(bf[nj], s0 + BOF + SWZ(ro));
            }
#pragma unroll
            for (int mi = 0; mi < 4; mi++)
#pragma unroll
                for (int nj = 0; nj < 2; nj++) {
                    mma16816(acc[mi][2*nj],   af[mi], bf[nj][0], bf[nj][2]);
                    mma16816(acc[mi][2*nj+1], af[mi], bf[nj][1], bf[nj][3]);
                }
        }
        __syncthreads();
    }
}

// ---------------- merged GEMM: z=0 common (dense), z>=1 expert (gathered) ----
__global__ __launch_bounds__(256, 2) void gemm_all(
    const float* __restrict__ bc, const float* __restrict__ be)
{
    extern __shared__ __align__(1024) char dsm[];
    const int z = blockIdx.z;
    const bool dense = (z == 0);
    const int fe = z - 1;
    const int t0 = blockIdx.x * BM;
    int cnt = 0;
    if (!dense) {
        cnt = g_cnt[fe];
        if (t0 >= cnt) return;
    }

    const int tid = threadIdx.x;
    const int w = tid >> 5, lane = tid & 31;
    const int n0 = blockIdx.y * BN;
    const int wm = (w & 1) * 64;
    const int wn = (w >> 1) * 32;
    uint32_t sb = s2u(dsm);
    int* sidx = (int*)(dsm + IDX_OFF);

    if (!dense) {
        if (tid < BM) {
            int s = t0 + tid;
            sidx[tid] = g_idx[fe][(s < cnt) ? s : (cnt - 1)];
        }
        __syncthreads();
    }

    const int ez = dense ? 0 : (1 + fe);
    const __half* wb = g_wh + (size_t)ez * Uu * Dd;

    float acc[4][4][4];
#pragma unroll
    for (int mi = 0; mi < 4; mi++)
#pragma unroll
        for (int ni = 0; ni < 4; ni++)
#pragma unroll
            for (int j = 0; j < 4; j++) acc[mi][ni][j] = 0.f;

    gemm_mainloop(sb, wb, dense ? nullptr : sidx, t0, n0, tid, lane, wm, wn, acc);

    if (dense) {
        const float* bep = bc + n0;
#pragma unroll
        for (int mi = 0; mi < 4; mi++) {
#pragma unroll
            for (int h = 0; h < 2; h++) {
                int rl = wm + mi * 16 + (lane >> 2) + h * 8;
                __half* gp = g_common + (size_t)(t0 + rl) * Uu + n0;
#pragma unroll
                for (int ni = 0; ni < 4; ni++) {
                    int cl = wn + ni * 8 + (lane & 3) * 2;
                    float v0 = fmaxf(acc[mi][ni][h * 2 + 0] + bep[cl],     0.f);
                    float v1 = fmaxf(acc[mi][ni][h * 2 + 1] + bep[cl + 1], 0.f);
                    *(__half2*)(gp + cl) = __floats2half2_rn(v0, v1);
                }
            }
        }
    } else {
        const int f = fe >> 2;
        const float* bep = be + (size_t)fe * Uu + n0;
        const bool atom = (f < 2);
#pragma unroll
        for (int mi = 0; mi < 4; mi++) {
#pragma unroll
            for (int h = 0; h < 2; h++) {
                int rl = wm + mi * 16 + (lane >> 2) + h * 8;
                if (t0 + rl >= cnt) continue;
                int grow = sidx[rl];
                __half* gp = g_field + (size_t)grow * (Ff * Uu) + (size_t)f * Uu + n0;
#pragma unroll
                for (int ni = 0; ni < 4; ni++) {
                    int cl = wn + ni * 8 + (lane & 3) * 2;
                    float v0 = fmaxf(acc[mi][ni][h * 2 + 0] + bep[cl],     0.f);
                    float v1 = fmaxf(acc[mi][ni][h * 2 + 1] + bep[cl + 1], 0.f);
                    __half2 hv = __floats2half2_rn(v0, v1);
                    if (atom) atomicAdd((__half2*)(gp + cl), hv);
                    else      *(__half2*)(gp + cl) = hv;
                }
            }
        }
    }
}

// ============================================================
// epilogue: warp-per-row, Wa/Wu staged once per block, no inner barriers
// ============================================================
#define EPI_BLOCKS 256
__global__ __launch_bounds__(256) void epilogue_kernel(
    const float* __restrict__ Wa, const float* __restrict__ ba,
    const float* __restrict__ Wu, const float* __restrict__ bu,
    float* __restrict__ out)
{
    __shared__ float wa_s[Ff * 2 * Uu];   // 16KB, [f][k] k<1024
    __shared__ float wu_s[Ff * 2 * Uu];   // 16KB
    const int tid = threadIdx.x;
    for (int i = tid; i < Ff * 2 * Uu; i += 256) {
        wa_s[i] = Wa[i];
        wu_s[i] = Wu[i];
    }
    __syncthreads();

    const int w = tid >> 5, lane = tid & 31;
    float bav[Ff], buv[Ff];
#pragma unroll
    for (int f = 0; f < Ff; f++) { bav[f] = ba[f]; buv[f] = bu[f]; }

    for (int b = blockIdx.x * 8 + w; b < Bsz; b += EPI_BLOCKS * 8) {
        // row data in registers (half2): lane owns u = 2*(lane+32j)+{0,1}
        __half2 ch[8];
        const __half2* cp = (const __half2*)(g_common + (size_t)b * Uu);
#pragma unroll
        for (int j = 0; j < 8; j++) ch[j] = cp[lane + 32 * j];
        __half2 fh[32];
        const __half2* fp = (const __half2*)(g_field + (size_t)b * Ff * Uu);
#pragma unroll
        for (int j = 0; j < 32; j++) fh[j] = fp[lane + 32 * j];

        // att/upd dots
        float sa[Ff] = {0.f, 0.f, 0.f, 0.f}, su[Ff] = {0.f, 0.f, 0.f, 0.f};
#pragma unroll
        for (int j = 0; j < 8; j++) {
            float2 v = __half22float2(ch[j]);
            int u0 = 2 * (lane + 32 * j);
#pragma unroll
            for (int f = 0; f < Ff; f++) {
                sa[f] = fmaf(v.x, wa_s[f * 1024 + u0],     sa[f]);
                sa[f] = fmaf(v.y, wa_s[f * 1024 + u0 + 1], sa[f]);
                su[f] = fmaf(v.x, wu_s[f * 1024 + u0],     su[f]);
                su[f] = fmaf(v.y, wu_s[f * 1024 + u0 + 1], su[f]);
            }
        }
#pragma unroll
        for (int j2 = 0; j2 < 32; j2++) {
            int f = j2 >> 3;
            int u0 = 2 * (lane + 32 * (j2 & 7));
            float2 v = __half22float2(fh[j2]);
            sa[f] = fmaf(v.x, wa_s[f * 1024 + 512 + u0],     sa[f]);
            sa[f] = fmaf(v.y, wa_s[f * 1024 + 512 + u0 + 1], sa[f]);
            su[f] = fmaf(v.x, wu_s[f * 1024 + 512 + u0],     su[f]);
            su[f] = fmaf(v.y, wu_s[f * 1024 + 512 + u0 + 1], su[f]);
        }
#pragma unroll
        for (int f = 0; f < Ff; f++) {
#pragma unroll
            for (int o = 16; o; o >>= 1) {
                sa[f] += __shfl_xor_sync(0xffffffffu, sa[f], o);
                su[f] += __shfl_xor_sync(0xffffffffu, su[f], o);
            }
            sa[f] = 1.f / (1.f + expf(-(sa[f] + bav[f])));
            su[f] = 1.f / (1.f + expf(-(su[f] + buv[f])));
        }

        // gates (every lane computes full softmax from shuffled logits)
        float lgv = (lane < Tt * Gg) ? g_logits[(size_t)b * (Tt * Gg) + lane] : 0.f;
        float lg[Tt * Gg];
#pragma unroll
        for (int j = 0; j < Tt * Gg; j++) lg[j] = __shfl_sync(0xffffffffu, lgv, j);
        float gates[Tt][Gg];
#pragma unroll
        for (int t = 0; t < Tt; t++) {
            float mx = lg[t * Gg];
#pragma unroll
            for (int g = 1; g < Gg; g++) mx = fmaxf(mx, lg[t * Gg + g]);
            float sum = 0.f;
#pragma unroll
            for (int g = 0; g < Gg; g++) { gates[t][g] = expf(lg[t * Gg + g] - mx); sum += gates[t][g]; }
            float inv = 1.f / sum;
#pragma unroll
            for (int g = 0; g < Gg; g++) gates[t][g] *= inv;
        }

        // mix + write
        float2* o0p = (float2*)(out + ((size_t)b * Tt + 0) * Uu);
        float2* o1p = (float2*)(out + ((size_t)b * Tt + 1) * Uu);
#pragma unroll
        for (int j = 0; j < 8; j++) {
            float2 c = __half22float2(ch[j]);
            float fx[Ff], fy[Ff];
#pragma unroll
            for (int f = 0; f < Ff; f++) {
                float2 fo = __half22float2(fh[f * 8 + j]);
                fx[f] = su[f] * (sa[f] * fo.x) + (1.f - su[f]) * c.x;
                fy[f] = su[f] * (sa[f] * fo.y) + (1.f - su[f]) * c.y;
            }
            float a0 = gates[0][0] * c.x, b0 = gates[0][0] * c.y;
            float a1 = gates[1][0] * c.x, b1 = gates[1][0] * c.y;
#pragma unroll
            for (int f = 0; f < Ff; f++) {
                a0 = fmaf(gates[0][1 + f], fx[f], a0);
                b0 = fmaf(gates[0][1 + f], fy[f], b0);
                a1 = fmaf(gates[1][1 + f], fx[f], a1);
                b1 = fmaf(gates[1][1 + f], fy[f], b1);
            }
            o0p[lane + 32 * j] = make_float2(a0, b0);
            o1p[lane + 32 * j] = make_float2(a1, b1);
        }
    }
}

// ============================================================
// launch
// ============================================================
extern "C" void kernel_launch(void* const* d_in, const int* in_sizes, int n_in,
                              void* d_out, int out_size)
{
    const float* x  = (const float*)d_in[0];
    const float* Wc = (const float*)d_in[1];
    const float* bc = (const float*)d_in[2];
    const float* We = (const float*)d_in[3];
    const float* be = (const float*)d_in[4];
    const float* Wg = (const float*)d_in[5];
    const float* bg = (const float*)d_in[6];
    const float* Wa = (const float*)d_in[7];
    const float* ba = (const float*)d_in[8];
    const float* Wu = (const float*)d_in[9];
    const float* bu = (const float*)d_in[10];
    float* out = (float*)d_out;

    cudaFuncSetAttribute(gemm_all, cudaFuncAttributeMaxDynamicSharedMemorySize, DSM_TOTAL);

    zero_cnt<<<1, 32>>>();
    prep_merged<<<PREP_BLOCKS + SPLITW_BLOCKS, 256>>>(x, Wg, bg, Wc, We);
    gemm_all<<<dim3(Bsz / BM, Uu / BN, 1 + Ff * Ee), 256, DSM_TOTAL>>>(bc, be);
    epilogue_kernel<<<EPI_BLOCKS, 256>>>(Wa, ba, Wu, bu, out);
}

// round 16
// speedup vs baseline: 2.7307x; 1.0352x over previous
#include <cuda_runtime.h>
#include <cuda_fp16.h>
#include <math.h>
#include <stdint.h>

// ---------------- problem constants ----------------
#define Bsz 8192
#define Dd  1024
#define Uu  512
#define Ff  4
#define Ee  4
#define Tt  2
#define Gg  5
#define NEXP 17

// ---------------- scratch ----------------
__device__ __half g_common[Bsz * Uu];                 // fp16 intermediates
__device__ __half g_field [Bsz * Ff * Uu];
__device__ float  g_logits[Bsz * Tt * Gg];
__device__ int    g_idx[Ff * Ee][Bsz];
__device__ int    g_cnt[Ff * Ee];
__device__ __half g_xh[Bsz * Dd];                     // fp16 x
__device__ __half g_wh[(size_t)NEXP * Uu * Dd];       // fp16 W, transposed [ez][u][d]

// ---------------- GEMM config: CTA 128x128, 8 warps (64x32), 2 CTAs/SM ----
#define BM 128
#define BN 128
#define NCH 16
#define AOF 0
#define BOF 16384
#define STAGE 32768
#define NSTG 2
#define IDX_OFF (NSTG * STAGE)
#define DSM_TOTAL (NSTG * STAGE + 1024)

#define SWZ(o) ((o) ^ (((o) >> 3) & 0x70))

__device__ __forceinline__ uint32_t s2u(const void* p) {
    return (uint32_t)__cvta_generic_to_shared(p);
}

__device__ __forceinline__ void cpa16(uint32_t dst, const void* src) {
    asm volatile("cp.async.cg.shared.global [%0], [%1], 16;"
                 :: "r"(dst), "l"(__cvta_generic_to_global(src)));
}
#define CP_COMMIT() asm volatile("cp.async.commit_group;" ::: "memory")
#define CP_WAIT(n)  asm volatile("cp.async.wait_group %0;" :: "n"(n) : "memory")

__device__ __forceinline__ void ldsm4(uint32_t* r, uint32_t addr) {
    asm volatile("ldmatrix.sync.aligned.m8n8.x4.shared.b16 {%0,%1,%2,%3}, [%4];"
                 : "=r"(r[0]), "=r"(r[1]), "=r"(r[2]), "=r"(r[3]) : "r"(addr));
}

__device__ __forceinline__ void mma16816(float* c, const uint32_t* a, uint32_t b0, uint32_t b1) {
    asm volatile(
        "mma.sync.aligned.m16n8k16.row.col.f32.f16.f16.f32 "
        "{%0,%1,%2,%3}, {%4,%5,%6,%7}, {%8,%9}, {%0,%1,%2,%3};"
        : "+f"(c[0]), "+f"(c[1]), "+f"(c[2]), "+f"(c[3])
        : "r"(a[0]), "r"(a[1]), "r"(a[2]), "r"(a[3]), "r"(b0), "r"(b1));
}

// issue one k-chunk (64 k-elems): A 128x128B + B 128x128B
__device__ __forceinline__ void issue_chunk(uint32_t sb, int ch,
                                            const __half* __restrict__ wb,
                                            const int* __restrict__ sidx,
                                            int m0, int n0, int tid)
{
    uint32_t st = sb + (uint32_t)(ch & (NSTG - 1)) * STAGE;
    const int kbase = ch * 64;
#pragma unroll
    for (int i = 0; i < 4; i++) {
        int u = tid + i * 256, r = u >> 3, cc = u & 7;
        int grow = sidx ? sidx[r] : (m0 + r);
        size_t go = (size_t)grow * Dd + kbase + cc * 8;
        cpa16(st + AOF + SWZ(r * 128 + cc * 16), g_xh + go);
    }
#pragma unroll
    for (int i = 0; i < 4; i++) {
        int u = tid + i * 256, r = u >> 3, cc = u & 7;
        size_t go = (size_t)(n0 + r) * Dd + kbase + cc * 8;
        cpa16(st + BOF + SWZ(r * 128 + cc * 16), wb + go);
    }
    CP_COMMIT();
}

// ============================================================
// prep
// ============================================================
__global__ void zero_cnt()
{
    if (threadIdx.x < Ff * Ee) g_cnt[threadIdx.x] = 0;
}

#define PREP_BLOCKS (Bsz / 8)                 // 1024
#define SPLITW_BLOCKS (16 * 32 * NEXP)        // 8704

// merged prep: blocks [0,1024) per-row prep; rest transpose+convert W
__global__ __launch_bounds__(256) void prep_merged(
    const float* __restrict__ x, const float* __restrict__ Wg,
    const float* __restrict__ bg,
    const float* __restrict__ Wc, const float* __restrict__ We)
{
    __shared__ float smem_f[Dd * Tt * Gg];
    const int tid = threadIdx.x;

    if (blockIdx.x < PREP_BLOCKS) {
        float* wgs = smem_f;
        for (int i = tid; i < Dd * Tt * Gg; i += 256) {
            int d = i / (Tt * Gg), tg = i - d * (Tt * Gg);
            int t = tg / Gg, g = tg - t * Gg;
            wgs[i] = Wg[((size_t)t * Dd + d) * Gg + g];
        }
        __syncthreads();

        const int w = tid >> 5, lane = tid & 31;
        const int b = blockIdx.x * 8 + w;
        const float* xr = x + (size_t)b * Dd;

        float acc[Tt * Gg];
#pragma unroll
        for (int j = 0; j < Tt * Gg; j++) acc[j] = 0.f;

#pragma unroll
        for (int j = 0; j < 8; j++) {
            int k4 = lane + j * 32;
            float4 v = ((const float4*)xr)[k4];
            __half2* dst = (__half2*)(g_xh + (size_t)b * Dd + k4 * 4);
            dst[0] = __floats2half2_rn(v.x, v.y);
            dst[1] = __floats2half2_rn(v.z, v.w);
            const float* wr = wgs + (k4 * 4) * (Tt * Gg);
            float vv[4] = {v.x, v.y, v.z, v.w};
#pragma unroll
            for (int q = 0; q < 4; q++)
#pragma unroll
                for (int jj = 0; jj < Tt * Gg; jj++)
                    acc[jj] = fmaf(vv[q], wr[q * (Tt * Gg) + jj], acc[jj]);
        }
#pragma unroll
        for (int jj = 0; jj < Tt * Gg; jj++)
#pragma unroll
            for (int o = 16; o; o >>= 1) acc[jj] += __shfl_xor_sync(0xffffffffu, acc[jj], o);
        if (lane < Tt * Gg)
            g_logits[(size_t)b * (Tt * Gg) + lane] = acc[lane] + bg[lane];

        uint4* zp = (uint4*)(g_field + (size_t)b * (Ff * Uu));
#pragma unroll
        for (int j = 0; j < 4; j++) zp[lane + j * 32] = make_uint4(0u, 0u, 0u, 0u);

        if (lane < 8) {
            if (xr[lane] > 0.f) {
                int p = atomicAdd(&g_cnt[lane], 1);
                g_idx[lane][p] = b;
            }
        } else if (lane < 10) {
            int f = 2 + (lane - 8);
            float v = xr[8 + (lane - 8)];
            int e = (v <= -0.5f) ? 0 : (v <= 0.f) ? 1 : (v <= 0.5f) ? 2 : 3;
            int fe = f * 4 + e;
            int p = atomicAdd(&g_cnt[fe], 1);
            g_idx[fe][p] = b;
        }
    } else {
        float (*t)[33] = (float(*)[33])smem_f;
        int i = blockIdx.x - PREP_BLOCKS;
        int ez = i >> 9;
        int rem = i & 511;
        int u0 = (rem & 15) * 32;
        int d0 = (rem >> 4) * 32;
        const float* src = (ez == 0) ? Wc : (We + (size_t)(ez - 1) * Dd * Uu);
        int tx = tid & 31, ty = tid >> 5;
#pragma unroll
        for (int k = 0; k < 32; k += 8)
            t[ty + k][tx] = src[(size_t)(d0 + ty + k) * Uu + u0 + tx];
        __syncthreads();
#pragma unroll
        for (int k = 0; k < 32; k += 8) {
            int u = u0 + ty + k, d = d0 + tx;
            g_wh[(size_t)ez * Uu * Dd + (size_t)u * Dd + d] = __float2half_rn(t[tx][ty + k]);
        }
    }
}

// ============================================================
// GEMM mainloop: single fp16 pass, warp tile 64x32 (frozen)
// ============================================================
__device__ __forceinline__ void gemm_mainloop(
    uint32_t sb, const __half* wb, const int* sidx,
    int m0, int n0, int tid, int lane, int wm, int wn,
    float acc[4][4][4])
{
    const int lrow = (lane & 7) + ((lane >> 3) & 1) * 8;
    const int kb   = lane >> 4;

    issue_chunk(sb, 0, wb, sidx, m0, n0, tid);

    for (int ch = 0; ch < NCH; ch++) {
        if (ch + 1 < NCH) {
            issue_chunk(sb, ch + 1, wb, sidx, m0, n0, tid);
            CP_WAIT(1);
        } else {
            CP_WAIT(0);
        }
        __syncthreads();

        uint32_t s0 = sb + (uint32_t)(ch & (NSTG - 1)) * STAGE;
#pragma unroll
        for (int ks = 0; ks < 4; ks++) {
            uint32_t koff = (uint32_t)(ks * 2 + kb) * 16;
            uint32_t af[4][4], bf[2][4];
#pragma unroll
            for (int mi = 0; mi < 4; mi++) {
                uint32_t ro = (uint32_t)(wm + mi * 16 + lrow) * 128 + koff;
                ldsm4(af[mi], s0 + AOF + SWZ(ro));
            }
#pragma unroll
            for (int nj = 0; nj < 2; nj++) {
                uint32_t ro = (uint32_t)(wn + nj * 16 + lrow) * 128 + koff;
                ldsm4(bf[nj], s0 + BOF + SWZ(ro));
            }
#pragma unroll
            for (int mi = 0; mi < 4; mi++)
#pragma unroll
                for (int nj = 0; nj < 2; nj++) {
                    mma16816(acc[mi][2*nj],   af[mi], bf[nj][0], bf[nj][2]);
                    mma16816(acc[mi][2*nj+1], af[mi], bf[nj][1], bf[nj][3]);
                }
        }
        __syncthreads();
    }
}

// ---------------- merged GEMM: z=0 common (dense), z>=1 expert (gathered) ----
__global__ __launch_bounds__(256, 2) void gemm_all(
    const float* __restrict__ bc, const float* __restrict__ be)
{
    extern __shared__ __align__(1024) char dsm[];
    const int z = blockIdx.z;
    const bool dense = (z == 0);
    const int fe = z - 1;
    const int t0 = blockIdx.x * BM;
    int cnt = 0;
    if (!dense) {
        cnt = g_cnt[fe];
        if (t0 >= cnt) return;
    }

    const int tid = threadIdx.x;
    const int w = tid >> 5, lane = tid & 31;
    const int n0 = blockIdx.y * BN;
    const int wm = (w & 1) * 64;
    const int wn = (w >> 1) * 32;
    uint32_t sb = s2u(dsm);
    int* sidx = (int*)(dsm + IDX_OFF);

    if (!dense) {
        if (tid < BM) {
            int s = t0 + tid;
            sidx[tid] = g_idx[fe][(s < cnt) ? s : (cnt - 1)];
        }
        __syncthreads();
    }

    const int ez = dense ? 0 : (1 + fe);
    const __half* wb = g_wh + (size_t)ez * Uu * Dd;

    float acc[4][4][4];
#pragma unroll
    for (int mi = 0; mi < 4; mi++)
#pragma unroll
        for (int ni = 0; ni < 4; ni++)
#pragma unroll
            for (int j = 0; j < 4; j++) acc[mi][ni][j] = 0.f;

    gemm_mainloop(sb, wb, dense ? nullptr : sidx, t0, n0, tid, lane, wm, wn, acc);

    if (dense) {
        const float* bep = bc + n0;
#pragma unroll
        for (int mi = 0; mi < 4; mi++) {
#pragma unroll
            for (int h = 0; h < 2; h++) {
                int rl = wm + mi * 16 + (lane >> 2) + h * 8;
                __half* gp = g_common + (size_t)(t0 + rl) * Uu + n0;
#pragma unroll
                for (int ni = 0; ni < 4; ni++) {
                    int cl = wn + ni * 8 + (lane & 3) * 2;
                    float v0 = fmaxf(acc[mi][ni][h * 2 + 0] + bep[cl],     0.f);
                    float v1 = fmaxf(acc[mi][ni][h * 2 + 1] + bep[cl + 1], 0.f);
                    *(__half2*)(gp + cl) = __floats2half2_rn(v0, v1);
                }
            }
        }
    } else {
        const int f = fe >> 2;
        const float* bep = be + (size_t)fe * Uu + n0;
        const bool atom = (f < 2);
#pragma unroll
        for (int mi = 0; mi < 4; mi++) {
#pragma unroll
            for (int h = 0; h < 2; h++) {
                int rl = wm + mi * 16 + (lane >> 2) + h * 8;
                if (t0 + rl >= cnt) continue;
                int grow = sidx[rl];
                __half* gp = g_field + (size_t)grow * (Ff * Uu) + (size_t)f * Uu + n0;
#pragma unroll
                for (int ni = 0; ni < 4; ni++) {
                    int cl = wn + ni * 8 + (lane & 3) * 2;
                    float v0 = fmaxf(acc[mi][ni][h * 2 + 0] + bep[cl],     0.f);
                    float v1 = fmaxf(acc[mi][ni][h * 2 + 1] + bep[cl + 1], 0.f);
                    __half2 hv = __floats2half2_rn(v0, v1);
                    if (atom) atomicAdd((__half2*)(gp + cl), hv);
                    else      *(__half2*)(gp + cl) = hv;
                }
            }
        }
    }
}

// ============================================================
// epilogue: warp-per-row, Wa/Wu staged once per block,
// reg-capped (128) for 2 blocks/SM occupancy
// ============================================================
#define EPI_BLOCKS 592
__global__ __launch_bounds__(256, 2) void epilogue_kernel(
    const float* __restrict__ Wa, const float* __restrict__ ba,
    const float* __restrict__ Wu, const float* __restrict__ bu,
    float* __restrict__ out)
{
    __shared__ float wa_s[Ff * 2 * Uu];   // 16KB
    __shared__ float wu_s[Ff * 2 * Uu];   // 16KB
    const int tid = threadIdx.x;
    for (int i = tid; i < Ff * 2 * Uu; i += 256) {
        wa_s[i] = Wa[i];
        wu_s[i] = Wu[i];
    }
    __syncthreads();

    const int w = tid >> 5, lane = tid & 31;

    for (int b = blockIdx.x * 8 + w; b < Bsz; b += EPI_BLOCKS * 8) {
        // issue ALL row loads first (max MLP), data lives in half2 regs
        __half2 ch[8];
        const __half2* cp = (const __half2*)(g_common + (size_t)b * Uu);
#pragma unroll
        for (int j = 0; j < 8; j++) ch[j] = cp[lane + 32 * j];
        __half2 fh[32];
        const __half2* fp = (const __half2*)(g_field + (size_t)b * Ff * Uu);
#pragma unroll
        for (int j = 0; j < 32; j++) fh[j] = fp[lane + 32 * j];
        float lgv = (lane < Tt * Gg) ? g_logits[(size_t)b * (Tt * Gg) + lane] : 0.f;

        // att/upd dots
        float sa[Ff] = {0.f, 0.f, 0.f, 0.f}, su[Ff] = {0.f, 0.f, 0.f, 0.f};
#pragma unroll
        for (int j = 0; j < 8; j++) {
            float2 v = __half22float2(ch[j]);
            int u0 = 2 * (lane + 32 * j);
#pragma unroll
            for (int f = 0; f < Ff; f++) {
                sa[f] = fmaf(v.x, wa_s[f * 1024 + u0],     sa[f]);
                sa[f] = fmaf(v.y, wa_s[f * 1024 + u0 + 1], sa[f]);
                su[f] = fmaf(v.x, wu_s[f * 1024 + u0],     su[f]);
                su[f] = fmaf(v.y, wu_s[f * 1024 + u0 + 1], su[f]);
            }
        }
#pragma unroll
        for (int j2 = 0; j2 < 32; j2++) {
            int f = j2 >> 3;
            int u0 = 2 * (lane + 32 * (j2 & 7));
            float2 v = __half22float2(fh[j2]);
            sa[f] = fmaf(v.x, wa_s[f * 1024 + 512 + u0],     sa[f]);
            sa[f] = fmaf(v.y, wa_s[f * 1024 + 512 + u0 + 1], sa[f]);
            su[f] = fmaf(v.x, wu_s[f * 1024 + 512 + u0],     su[f]);
            su[f] = fmaf(v.y, wu_s[f * 1024 + 512 + u0 + 1], su[f]);
        }
#pragma unroll
        for (int f = 0; f < Ff; f++) {
#pragma unroll
            for (int o = 16; o; o >>= 1) {
                sa[f] += __shfl_xor_sync(0xffffffffu, sa[f], o);
                su[f] += __shfl_xor_sync(0xffffffffu, su[f], o);
            }
            sa[f] = 1.f / (1.f + expf(-(sa[f] + ba[f])));
            su[f] = 1.f / (1.f + expf(-(su[f] + bu[f])));
        }

        // gates (each lane computes full softmax from shuffled logits)
        float lg[Tt * Gg];
#pragma unroll
        for (int j = 0; j < Tt * Gg; j++) lg[j] = __shfl_sync(0xffffffffu, lgv, j);
        float gates[Tt][Gg];
#pragma unroll
        for (int t = 0; t < Tt; t++) {
            float mx = lg[t * Gg];
#pragma unroll
            for (int g = 1; g < Gg; g++) mx = fmaxf(mx, lg[t * Gg + g]);
            float sum = 0.f;
#pragma unroll
            for (int g = 0; g < Gg; g++) { gates[t][g] = expf(lg[t * Gg + g] - mx); sum += gates[t][g]; }
            float inv = 1.f / sum;
#pragma unroll
            for (int g = 0; g < Gg; g++) gates[t][g] *= inv;
        }

        // mix + write
        float2* o0p = (float2*)(out + ((size_t)b * Tt + 0) * Uu);
        float2* o1p = (float2*)(out + ((size_t)b * Tt + 1) * Uu);
#pragma unroll
        for (int j = 0; j < 8; j++) {
            float2 c = __half22float2(ch[j]);
            float a0 = gates[0][0] * c.x, b0 = gates[0][0] * c.y;
            float a1 = gates[1][0] * c.x, b1 = gates[1][0] * c.y;
#pragma unroll
            for (int f = 0; f < Ff; f++) {
                float2 fo = __half22float2(fh[f * 8 + j]);
                float fx = su[f] * (sa[f] * fo.x) + (1.f - su[f]) * c.x;
                float fy = su[f] * (sa[f] * fo.y) + (1.f - su[f]) * c.y;
                a0 = fmaf(gates[0][1 + f], fx, a0);
                b0 = fmaf(gates[0][1 + f], fy, b0);
                a1 = fmaf(gates[1][1 + f], fx, a1);
                b1 = fmaf(gates[1][1 + f], fy, b1);
            }
            o0p[lane + 32 * j] = make_float2(a0, b0);
            o1p[lane + 32 * j] = make_float2(a1, b1);
        }
    }
}

// ============================================================
// launch
// ============================================================
extern "C" void kernel_launch(void* const* d_in, const int* in_sizes, int n_in,
                              void* d_out, int out_size)
{
    const float* x  = (const float*)d_in[0];
    const float* Wc = (const float*)d_in[1];
    const float* bc = (const float*)d_in[2];
    const float* We = (const float*)d_in[3];
    const float* be = (const float*)d_in[4];
    const float* Wg = (const float*)d_in[5];
    const float* bg = (const float*)d_in[6];
    const float* Wa = (const float*)d_in[7];
    const float* ba = (const float*)d_in[8];
    const float* Wu = (const float*)d_in[9];
    const float* bu = (const float*)d_in[10];
    float* out = (float*)d_out;

    cudaFuncSetAttribute(gemm_all, cudaFuncAttributeMaxDynamicSharedMemorySize, DSM_TOTAL);

    zero_cnt<<<1, 32>>>();
    prep_merged<<<PREP_BLOCKS + SPLITW_BLOCKS, 256>>>(x, Wg, bg, Wc, We);
    gemm_all<<<dim3(Bsz / BM, Uu / BN, 1 + Ff * Ee), 256, DSM_TOTAL>>>(bc, be);
    epilogue_kernel<<<EPI_BLOCKS, 256>>>(Wa, ba, Wu, bu, out);
}